// round 9
// baseline (speedup 1.0000x reference)
#include <cuda_runtime.h>
#include <cuda_fp16.h>
#include <math.h>
#include <stdint.h>

// ---------------------------------------------------------------------------
// Problem constants
// ---------------------------------------------------------------------------
#define S_LEN 256
#define B_SZ  32
#define E_DIM 300
#define H_DIM 2400
#define N3H   (3 * H_DIM)            // 7200
#define M_ROWS (S_LEN * B_SZ)        // 8192

#define K1PAD 320                    // 300 -> mult of 64
#define K2PAD 2432                   // 2400 -> mult of 64
#define NPAD  7424                   // 7200 -> mult of 256

#define BM 128
#define BN 256
#define BK 64
#define NSTAGE 3
#define NGRP (NPAD / BN)             // 29
#define NTHREADS 512

// SMEM planes: rows x 64 fp16 (128 B) padded to 144 B (conflict-free ldmatrix)
#define ROWB 144
#define A_PLANE (128 * ROWB)         // 18432
#define B_PLANE (256 * ROWB)         // 36864
#define OFF_A   0
#define OFF_B   A_PLANE
#define STAGE_BYTES (A_PLANE + B_PLANE)          // 55296
#define GEMM_SMEM_BYTES (NSTAGE * STAGE_BYTES)   // 165888 (1 CTA/SM)

// ---------------------------------------------------------------------------
// Scratch (__device__ globals: allocation-free; zero-initialized at load,
// so padded K/N regions read as 0)
// ---------------------------------------------------------------------------
__device__ __align__(16) __half g_A1[(size_t)M_ROWS * K1PAD];
__device__ __align__(16) __half g_Ax[(size_t)M_ROWS * K2PAD];
__device__ __align__(16) __half g_W1[(size_t)NPAD * K1PAD];
__device__ __align__(16) __half g_W2[(size_t)NPAD * K2PAD];
__device__ __align__(16) __half g_W3[(size_t)NPAD * K2PAD];
__device__ __align__(16) __half g_gates[(size_t)M_ROWS * N3H];   // fp16 gates
__device__ float g_acc[B_SZ * H_DIM];

// ---------------------------------------------------------------------------
__device__ __forceinline__ uint32_t smem_u32(const void* p) {
    uint32_t a;
    asm("{ .reg .u64 t; cvta.to.shared.u64 t, %1; cvt.u32.u64 %0, t; }" : "=r"(a) : "l"(p));
    return a;
}
__device__ __forceinline__ float sigmoid_f(float x) {
    return __fdividef(1.0f, 1.0f + __expf(-x));
}
__device__ __forceinline__ float tanh_fast(float x) {
    return 1.0f - __fdividef(2.0f, __expf(2.0f * x) + 1.0f);
}

#define CP_ASYNC16(dst, src) \
    asm volatile("cp.async.cg.shared.global [%0], [%1], 16;" :: "r"(dst), "l"(src) : "memory")
#define CP_COMMIT() asm volatile("cp.async.commit_group;" ::: "memory")
#define CP_WAIT(n)  asm volatile("cp.async.wait_group %0;" :: "n"(n) : "memory")

#define LDSM_X4(r0, r1, r2, r3, addr) \
    asm volatile("ldmatrix.sync.aligned.m8n8.x4.shared.b16 {%0,%1,%2,%3}, [%4];" \
                 : "=r"(r0), "=r"(r1), "=r"(r2), "=r"(r3) : "r"(addr))

#define MMA_FP16(d, a, b0, b1) \
    asm volatile("mma.sync.aligned.m16n8k16.row.col.f32.f16.f16.f32 " \
                 "{%0,%1,%2,%3}, {%4,%5,%6,%7}, {%8,%9}, {%0,%1,%2,%3};" \
                 : "+f"((d)[0]), "+f"((d)[1]), "+f"((d)[2]), "+f"((d)[3]) \
                 : "r"((a)[0]), "r"((a)[1]), "r"((a)[2]), "r"((a)[3]), "r"(b0), "r"(b1))

// ---------------------------------------------------------------------------
// fp32 -> fp16 conversions, vectorized
// ---------------------------------------------------------------------------
__global__ void cvt_W_kernel(const float* __restrict__ in, int K4, int Kpad, int which) {
    __half* w = (which == 0) ? g_W1 : (which == 1) ? g_W2 : g_W3;
    const int r = blockIdx.x;
    const float4* row = (const float4*)(in + (size_t)r * (K4 * 4));
    for (int k4 = threadIdx.x; k4 < K4; k4 += blockDim.x) {
        const float4 x = row[k4];
        __half2 h01 = __floats2half2_rn(x.x, x.y);
        __half2 h23 = __floats2half2_rn(x.z, x.w);
        uint2 ph;
        ph.x = *(uint32_t*)&h01; ph.y = *(uint32_t*)&h23;
        *(uint2*)(w + (size_t)r * Kpad + k4 * 4) = ph;
    }
}

__global__ void cvt_A1_kernel(const float* __restrict__ sent) {
    const int r = blockIdx.x;
    const float4* row = (const float4*)(sent + (size_t)r * E_DIM);
    for (int k4 = threadIdx.x; k4 < E_DIM / 4; k4 += blockDim.x) {
        const float4 x = row[k4];
        __half2 h01 = __floats2half2_rn(x.x, x.y);
        __half2 h23 = __floats2half2_rn(x.z, x.w);
        uint2 ph;
        ph.x = *(uint32_t*)&h01; ph.y = *(uint32_t*)&h23;
        *(uint2*)(g_A1 + (size_t)r * K1PAD + k4 * 4) = ph;
    }
}

// ---------------------------------------------------------------------------
// fp16 HMMA GEMM (fp32 accum): g_gates[m,n] = act( A[m,:].W[n,:] + bias[n] )
// BM=128, BN=256, BK=64, 512 threads (16 warps, 2x8, 64x32 warp tile),
// 3-stage cp.async pipeline, 1 CTA/SM.
// ---------------------------------------------------------------------------
__global__ __launch_bounds__(NTHREADS, 1) void gemm_tc(int layer, const float* __restrict__ bias) {
    const __half *A, *W;
    int Kpad;
    if (layer == 1)      { A = g_A1; W = g_W1; Kpad = K1PAD; }
    else if (layer == 2) { A = g_Ax; W = g_W2; Kpad = K2PAD; }
    else                 { A = g_Ax; W = g_W3; Kpad = K2PAD; }
    const int NT = Kpad / BK;

    // m-strip swizzle for L2 reuse: strips of 8 m-groups, n fastest
    const int bx = blockIdx.x;
    const int strip = bx / (8 * NGRP);
    const int rem   = bx % (8 * NGRP);
    const int mg    = strip * 8 + (rem % 8);
    const int ng    = rem / 8;
    const int m0 = mg * BM;
    const int n0 = ng * BN;

    extern __shared__ char smem_raw[];
    const uint32_t sbase = smem_u32(smem_raw);

    const int tid = threadIdx.x;
    const int wid = tid >> 5;
    const int lid = tid & 31;
    const int wm = (wid & 1) * 64;       // 0 / 64
    const int wn = (wid >> 1) * 32;      // 0..224

    auto load_chunk = [&](int t, int slot) {
        const uint32_t st = sbase + (uint32_t)slot * STAGE_BYTES;
        const int kc = t * BK;
        // A: 128 rows x 8 16B-units = 1024 ops over 512 threads
#pragma unroll
        for (int i = 0; i < 2; i++) {
            const int u = tid + i * NTHREADS;
            const int r = u >> 3, c = u & 7;
            const uint32_t so = (uint32_t)(r * ROWB + c * 16);
            CP_ASYNC16(st + OFF_A + so, A + (size_t)(m0 + r) * Kpad + kc + c * 8);
        }
        // B: 256 rows x 8 units = 2048 ops
#pragma unroll
        for (int i = 0; i < 4; i++) {
            const int u = tid + i * NTHREADS;
            const int r = u >> 3, c = u & 7;
            const uint32_t so = (uint32_t)(r * ROWB + c * 16);
            CP_ASYNC16(st + OFF_B + so, W + (size_t)(n0 + r) * Kpad + kc + c * 8);
        }
        CP_COMMIT();
    };

    float d[4][4][4];
#pragma unroll
    for (int mi = 0; mi < 4; mi++)
#pragma unroll
        for (int ni = 0; ni < 4; ni++)
#pragma unroll
            for (int q = 0; q < 4; q++) d[mi][ni][q] = 0.0f;

    const uint32_t a_row = (uint32_t)(wm + (lid & 15));
    const uint32_t a_kb  = (uint32_t)((lid >> 4) * 16);
    const uint32_t b_row = (uint32_t)(wn + (lid & 7) + ((lid >> 4) & 1) * 8);
    const uint32_t b_kb  = (uint32_t)(((lid >> 3) & 1) * 16);

    // Prologue: fill 2 of 3 stages
    load_chunk(0, 0);
    load_chunk(1, 1);

    for (int t = 0; t < NT; ++t) {
        CP_WAIT(1);            // chunk t landed (t+1 may still be in flight)
        __syncthreads();       // all warps done with the slot being refilled

        if (t + 2 < NT) load_chunk(t + 2, (t + 2) % NSTAGE);
        else CP_COMMIT();      // keep outstanding-group count uniform

        const uint32_t st = sbase + (uint32_t)(t % NSTAGE) * STAGE_BYTES;
#pragma unroll
        for (int ks = 0; ks < 4; ks++) {
            const uint32_t kbyte = (uint32_t)(ks * 32);
            uint32_t af[4][4];
#pragma unroll
            for (int mi = 0; mi < 4; mi++) {
                const uint32_t ra = st + OFF_A + (a_row + mi * 16) * ROWB + kbyte + a_kb;
                LDSM_X4(af[mi][0], af[mi][1], af[mi][2], af[mi][3], ra);
            }
            uint32_t bf[4][2];
#pragma unroll
            for (int j = 0; j < 2; j++) {
                const uint32_t rb = st + OFF_B + (b_row + j * 16) * ROWB + kbyte + b_kb;
                LDSM_X4(bf[2*j][0], bf[2*j][1], bf[2*j+1][0], bf[2*j+1][1], rb);
            }
#pragma unroll
            for (int mi = 0; mi < 4; mi++)
#pragma unroll
                for (int ni = 0; ni < 4; ni++)
                    MMA_FP16(d[mi][ni], af[mi], bf[ni][0], bf[ni][1]);
        }
    }

    __syncthreads();

    // Epilogue: bias + activation + fp16 store
    const int er = lid >> 2;
    const int ec = (lid & 3) * 2;
#pragma unroll
    for (int mi = 0; mi < 4; mi++) {
#pragma unroll
        for (int ni = 0; ni < 4; ni++) {
            const int n = n0 + wn + ni * 8 + ec;     // even; H_DIM even -> no straddle
            if (n >= N3H) continue;
            const int m = m0 + wm + mi * 16 + er;
            const float2 bs = *(const float2*)(bias + n);
            const bool tA = (n < H_DIM);
            {
                const float y0 = d[mi][ni][0] + bs.x;
                const float y1 = d[mi][ni][1] + bs.y;
                const float v0 = tA ? tanh_fast(y0) : sigmoid_f(y0);
                const float v1 = tA ? tanh_fast(y1) : sigmoid_f(y1);
                *(__half2*)(g_gates + (size_t)m * N3H + n) = __floats2half2_rn(v0, v1);
            }
            {
                const float y0 = d[mi][ni][2] + bs.x;
                const float y1 = d[mi][ni][3] + bs.y;
                const float v0 = tA ? tanh_fast(y0) : sigmoid_f(y0);
                const float v1 = tA ? tanh_fast(y1) : sigmoid_f(y1);
                *(__half2*)(g_gates + (size_t)(m + 8) * N3H + n) = __floats2half2_rn(v0, v1);
            }
        }
    }
}

// ---------------------------------------------------------------------------
// fo-pool scan: 4 h-lanes/thread, fp16 gate reads, fp32 recurrence.
// ---------------------------------------------------------------------------
__device__ __forceinline__ float4 ld_gates4(const __half* p) {
    const uint2 u = *(const uint2*)p;
    const float2 a = __half22float2(*(const __half2*)&u.x);
    const float2 b = __half22float2(*(const __half2*)&u.y);
    return make_float4(a.x, a.y, b.x, b.y);
}

__global__ void scan_kernel(int mode, const int* __restrict__ sent_len,
                            float* __restrict__ out)
{
    const int tix = blockIdx.x * blockDim.x + threadIdx.x;
    if (tix >= (B_SZ * H_DIM) / 4) return;
    const int flat = tix * 4;
    const int b = flat / H_DIM;
    const int h = flat - b * H_DIM;

    const size_t stride = (size_t)B_SZ * N3H;
    size_t base = (size_t)b * N3H + h;

    float4 c = make_float4(0.f, 0.f, 0.f, 0.f);

    if (mode != 2) {
        size_t xbase = (size_t)b * K2PAD + h;
        const size_t xstride = (size_t)B_SZ * K2PAD;
#pragma unroll 4
        for (int s = 0; s < S_LEN; ++s) {
            const float4 z = ld_gates4(g_gates + base);
            const float4 f = ld_gates4(g_gates + base + H_DIM);
            const float4 o = ld_gates4(g_gates + base + 2 * H_DIM);
            c.x = fmaf(f.x, c.x - z.x, z.x);
            c.y = fmaf(f.y, c.y - z.y, z.y);
            c.z = fmaf(f.z, c.z - z.z, z.z);
            c.w = fmaf(f.w, c.w - z.w, z.w);
            __half2 h01 = __floats2half2_rn(o.x * c.x, o.y * c.y);
            __half2 h23 = __floats2half2_rn(o.z * c.z, o.w * c.w);
            uint2 pk;
            pk.x = *(uint32_t*)&h01;
            pk.y = *(uint32_t*)&h23;
            *(uint2*)(g_Ax + xbase) = pk;
            base  += stride;
            xbase += xstride;
        }
    } else {
#pragma unroll 4
        for (int s = 0; s < S_LEN; ++s) {
            const float4 z = ld_gates4(g_gates + base);
            const float4 f = ld_gates4(g_gates + base + H_DIM);
            c.x = fmaf(f.x, c.x - z.x, z.x);
            c.y = fmaf(f.y, c.y - z.y, z.y);
            c.z = fmaf(f.z, c.z - z.z, z.z);
            c.w = fmaf(f.w, c.w - z.w, z.w);
            base += stride;
        }
    }

    if (mode == 0) {
        *(float4*)(g_acc + flat) = c;
    } else if (mode == 1) {
        float4 a = *(const float4*)(g_acc + flat);
        a.x += c.x; a.y += c.y; a.z += c.z; a.w += c.w;
        *(float4*)(g_acc + flat) = a;
    } else {
        const float inv = 1.0f / (float)sent_len[b];
        float4 a = *(const float4*)(g_acc + flat);
        float4 v;
        v.x = (a.x + c.x) * inv;
        v.y = (a.y + c.y) * inv;
        v.z = (a.z + c.z) * inv;
        v.w = (a.w + c.w) * inv;
        *(float4*)(out + flat) = v;
    }
}

// ---------------------------------------------------------------------------
extern "C" void kernel_launch(void* const* d_in, const int* in_sizes, int n_in,
                              void* d_out, int out_size)
{
    const float* sent     = (const float*)d_in[0];
    const int*   sent_len = (const int*)  d_in[1];
    const float* W1 = (const float*)d_in[2];
    const float* b1 = (const float*)d_in[3];
    const float* W2 = (const float*)d_in[4];
    const float* b2 = (const float*)d_in[5];
    const float* W3 = (const float*)d_in[6];
    const float* b3 = (const float*)d_in[7];
    float* out = (float*)d_out;

    cudaFuncSetAttribute(gemm_tc, cudaFuncAttributeMaxDynamicSharedMemorySize, GEMM_SMEM_BYTES);

    cvt_W_kernel<<<N3H, 128>>>(W1, E_DIM / 4, K1PAD, 0);
    cvt_W_kernel<<<N3H, 128>>>(W2, H_DIM / 4, K2PAD, 1);
    cvt_W_kernel<<<N3H, 128>>>(W3, H_DIM / 4, K2PAD, 2);
    cvt_A1_kernel<<<M_ROWS, 64>>>(sent);

    const int nblocks = (M_ROWS / BM) * NGRP;             // 64 * 29 = 1856
    const int sblocks = ((B_SZ * H_DIM) / 4 + 127) / 128; // 150

    gemm_tc<<<nblocks, NTHREADS, GEMM_SMEM_BYTES>>>(1, b1);
    scan_kernel<<<sblocks, 128>>>(0, sent_len, out);

    gemm_tc<<<nblocks, NTHREADS, GEMM_SMEM_BYTES>>>(2, b2);
    scan_kernel<<<sblocks, 128>>>(1, sent_len, out);

    gemm_tc<<<nblocks, NTHREADS, GEMM_SMEM_BYTES>>>(3, b3);
    scan_kernel<<<sblocks, 128>>>(2, sent_len, out);
}

// round 10
// speedup vs baseline: 1.1871x; 1.1871x over previous
#include <cuda_runtime.h>
#include <cuda_fp16.h>
#include <math.h>
#include <stdint.h>

// ---------------------------------------------------------------------------
// Problem constants
// ---------------------------------------------------------------------------
#define S_LEN 256
#define B_SZ  32
#define E_DIM 300
#define H_DIM 2400
#define N3H   (3 * H_DIM)            // 7200
#define M_ROWS (S_LEN * B_SZ)        // 8192

#define K1PAD 320                    // 300 -> mult of 64
#define K2PAD 2432                   // 2400 -> mult of 64
#define NPAD  7296                   // 7200 -> mult of 128

#define BM 128
#define BN 128
#define BK 64
#define NSTAGE 3
#define NGRP (NPAD / BN)             // 57

// SMEM plane: 128 rows x 64 fp16 (128 B) padded to 144 B (conflict-free ldmatrix)
#define ROWB 144
#define PLANE_BYTES (128 * ROWB)     // 18432
#define OFF_A   0
#define OFF_B   PLANE_BYTES
#define STAGE_BYTES (2 * PLANE_BYTES)            // 36864
#define GEMM_SMEM_BYTES (NSTAGE * STAGE_BYTES)   // 110592 (x2 CTA = 221184 <= 228K)

// ---------------------------------------------------------------------------
// Scratch (__device__ globals: allocation-free; zero-initialized at load,
// so padded K/N regions read as 0)
// ---------------------------------------------------------------------------
__device__ __align__(16) __half g_A1[(size_t)M_ROWS * K1PAD];
__device__ __align__(16) __half g_Ax[(size_t)M_ROWS * K2PAD];
__device__ __align__(16) __half g_W1[(size_t)NPAD * K1PAD];
__device__ __align__(16) __half g_W2[(size_t)NPAD * K2PAD];
__device__ __align__(16) __half g_W3[(size_t)NPAD * K2PAD];
__device__ __align__(16) __half g_gates[(size_t)M_ROWS * N3H];   // fp16 gates
__device__ float g_acc[B_SZ * H_DIM];

// ---------------------------------------------------------------------------
__device__ __forceinline__ uint32_t smem_u32(const void* p) {
    uint32_t a;
    asm("{ .reg .u64 t; cvta.to.shared.u64 t, %1; cvt.u32.u64 %0, t; }" : "=r"(a) : "l"(p));
    return a;
}
__device__ __forceinline__ float sigmoid_f(float x) {
    return __fdividef(1.0f, 1.0f + __expf(-x));
}
__device__ __forceinline__ float tanh_fast(float x) {
    return 1.0f - __fdividef(2.0f, __expf(2.0f * x) + 1.0f);
}

#define CP_ASYNC16(dst, src) \
    asm volatile("cp.async.cg.shared.global [%0], [%1], 16;" :: "r"(dst), "l"(src) : "memory")
#define CP_COMMIT() asm volatile("cp.async.commit_group;" ::: "memory")
#define CP_WAIT(n)  asm volatile("cp.async.wait_group %0;" :: "n"(n) : "memory")

#define LDSM_X4(r0, r1, r2, r3, addr) \
    asm volatile("ldmatrix.sync.aligned.m8n8.x4.shared.b16 {%0,%1,%2,%3}, [%4];" \
                 : "=r"(r0), "=r"(r1), "=r"(r2), "=r"(r3) : "r"(addr))

#define MMA_FP16(d, a, b0, b1) \
    asm volatile("mma.sync.aligned.m16n8k16.row.col.f32.f16.f16.f32 " \
                 "{%0,%1,%2,%3}, {%4,%5,%6,%7}, {%8,%9}, {%0,%1,%2,%3};" \
                 : "+f"((d)[0]), "+f"((d)[1]), "+f"((d)[2]), "+f"((d)[3]) \
                 : "r"((a)[0]), "r"((a)[1]), "r"((a)[2]), "r"((a)[3]), "r"(b0), "r"(b1))

// ---------------------------------------------------------------------------
// fp32 -> fp16 conversions, vectorized. One launch covers all three W's
// (blockIdx.y selects layer); A1 separate.
// ---------------------------------------------------------------------------
__global__ void cvt_W_all(const float* __restrict__ w1in,
                          const float* __restrict__ w2in,
                          const float* __restrict__ w3in) {
    const int which = blockIdx.y;
    const float* in;
    __half* w;
    int K4, Kpad;
    if (which == 0)      { in = w1in; w = g_W1; K4 = E_DIM / 4; Kpad = K1PAD; }
    else if (which == 1) { in = w2in; w = g_W2; K4 = H_DIM / 4; Kpad = K2PAD; }
    else                 { in = w3in; w = g_W3; K4 = H_DIM / 4; Kpad = K2PAD; }
    const int r = blockIdx.x;
    const float4* row = (const float4*)(in + (size_t)r * (K4 * 4));
    for (int k4 = threadIdx.x; k4 < K4; k4 += blockDim.x) {
        const float4 x = row[k4];
        __half2 h01 = __floats2half2_rn(x.x, x.y);
        __half2 h23 = __floats2half2_rn(x.z, x.w);
        uint2 ph;
        ph.x = *(uint32_t*)&h01; ph.y = *(uint32_t*)&h23;
        *(uint2*)(w + (size_t)r * Kpad + k4 * 4) = ph;
    }
}

__global__ void cvt_A1_kernel(const float* __restrict__ sent) {
    const int r = blockIdx.x;
    const float4* row = (const float4*)(sent + (size_t)r * E_DIM);
    for (int k4 = threadIdx.x; k4 < E_DIM / 4; k4 += blockDim.x) {
        const float4 x = row[k4];
        __half2 h01 = __floats2half2_rn(x.x, x.y);
        __half2 h23 = __floats2half2_rn(x.z, x.w);
        uint2 ph;
        ph.x = *(uint32_t*)&h01; ph.y = *(uint32_t*)&h23;
        *(uint2*)(g_A1 + (size_t)r * K1PAD + k4 * 4) = ph;
    }
}

// ---------------------------------------------------------------------------
// fp16 HMMA GEMM (fp32 accum): g_gates[m,n] = act( A[m,:].W[n,:] + bias[n] )
// BM=128, BN=128, BK=64, warp tile 64x32, 3-stage pipeline, 2 CTAs/SM. (R8)
// ---------------------------------------------------------------------------
__global__ __launch_bounds__(256, 2) void gemm_tc(int layer, const float* __restrict__ bias) {
    const __half *A, *W;
    int Kpad;
    if (layer == 1)      { A = g_A1; W = g_W1; Kpad = K1PAD; }
    else if (layer == 2) { A = g_Ax; W = g_W2; Kpad = K2PAD; }
    else                 { A = g_Ax; W = g_W3; Kpad = K2PAD; }
    const int NT = Kpad / BK;

    // m-strip swizzle for L2 reuse: strips of 8 m-groups, n fastest
    const int bx = blockIdx.x;
    const int strip = bx / (8 * NGRP);
    const int rem   = bx % (8 * NGRP);
    const int mg    = strip * 8 + (rem % 8);
    const int ng    = rem / 8;
    const int m0 = mg * BM;
    const int n0 = ng * BN;

    extern __shared__ char smem_raw[];
    const uint32_t sbase = smem_u32(smem_raw);

    const int tid = threadIdx.x;
    const int wid = tid >> 5;
    const int lid = tid & 31;
    const int wm = (wid & 1) * 64;
    const int wn = (wid >> 1) * 32;

    auto load_chunk = [&](int t, int slot) {
        const uint32_t st = sbase + (uint32_t)slot * STAGE_BYTES;
        const int kc = t * BK;
#pragma unroll
        for (int i = 0; i < 4; i++) {
            const int u = tid + i * 256;
            const int r = u >> 3, c = u & 7;
            const uint32_t so = (uint32_t)(r * ROWB + c * 16);
            CP_ASYNC16(st + OFF_A + so, A + (size_t)(m0 + r) * Kpad + kc + c * 8);
            CP_ASYNC16(st + OFF_B + so, W + (size_t)(n0 + r) * Kpad + kc + c * 8);
        }
        CP_COMMIT();
    };

    float d[4][4][4];
#pragma unroll
    for (int mi = 0; mi < 4; mi++)
#pragma unroll
        for (int ni = 0; ni < 4; ni++)
#pragma unroll
            for (int q = 0; q < 4; q++) d[mi][ni][q] = 0.0f;

    const uint32_t a_row = (uint32_t)(wm + (lid & 15));
    const uint32_t a_kb  = (uint32_t)((lid >> 4) * 16);
    const uint32_t b_row = (uint32_t)(wn + (lid & 7) + ((lid >> 4) & 1) * 8);
    const uint32_t b_kb  = (uint32_t)(((lid >> 3) & 1) * 16);

    // Prologue: fill 2 of 3 stages
    load_chunk(0, 0);
    load_chunk(1, 1);

    for (int t = 0; t < NT; ++t) {
        CP_WAIT(1);            // chunk t landed (t+1 may still be in flight)
        __syncthreads();       // all warps done with slot being refilled

        if (t + 2 < NT) load_chunk(t + 2, (t + 2) % NSTAGE);
        else CP_COMMIT();      // keep outstanding-group count uniform

        const uint32_t st = sbase + (uint32_t)(t % NSTAGE) * STAGE_BYTES;
#pragma unroll
        for (int ks = 0; ks < 4; ks++) {
            const uint32_t kbyte = (uint32_t)(ks * 32);
            uint32_t af[4][4];
#pragma unroll
            for (int mi = 0; mi < 4; mi++) {
                const uint32_t ra = st + OFF_A + (a_row + mi * 16) * ROWB + kbyte + a_kb;
                LDSM_X4(af[mi][0], af[mi][1], af[mi][2], af[mi][3], ra);
            }
            uint32_t bf[4][2];
#pragma unroll
            for (int j = 0; j < 2; j++) {
                const uint32_t rb = st + OFF_B + (b_row + j * 16) * ROWB + kbyte + b_kb;
                LDSM_X4(bf[2*j][0], bf[2*j][1], bf[2*j+1][0], bf[2*j+1][1], rb);
            }
#pragma unroll
            for (int mi = 0; mi < 4; mi++)
#pragma unroll
                for (int ni = 0; ni < 4; ni++)
                    MMA_FP16(d[mi][ni], af[mi], bf[ni][0], bf[ni][1]);
        }
    }

    __syncthreads();

    // Epilogue: bias + activation + fp16 store
    const int er = lid >> 2;
    const int ec = (lid & 3) * 2;
#pragma unroll
    for (int mi = 0; mi < 4; mi++) {
#pragma unroll
        for (int ni = 0; ni < 4; ni++) {
            const int n = n0 + wn + ni * 8 + ec;     // even; H_DIM even -> no straddle
            if (n >= N3H) continue;
            const int m = m0 + wm + mi * 16 + er;
            const float2 bs = *(const float2*)(bias + n);
            const bool tA = (n < H_DIM);
            {
                const float y0 = d[mi][ni][0] + bs.x;
                const float y1 = d[mi][ni][1] + bs.y;
                const float v0 = tA ? tanh_fast(y0) : sigmoid_f(y0);
                const float v1 = tA ? tanh_fast(y1) : sigmoid_f(y1);
                *(__half2*)(g_gates + (size_t)m * N3H + n) = __floats2half2_rn(v0, v1);
            }
            {
                const float y0 = d[mi][ni][2] + bs.x;
                const float y1 = d[mi][ni][3] + bs.y;
                const float v0 = tA ? tanh_fast(y0) : sigmoid_f(y0);
                const float v1 = tA ? tanh_fast(y1) : sigmoid_f(y1);
                *(__half2*)(g_gates + (size_t)(m + 8) * N3H + n) = __floats2half2_rn(v0, v1);
            }
        }
    }
}

// ---------------------------------------------------------------------------
// fo-pool scan: 2 h-lanes/thread (38400 threads -> 2x in-flight bytes vs R8),
// fp16 gate reads, fp32 recurrence.
// ---------------------------------------------------------------------------
__device__ __forceinline__ float2 ld_gates2(const __half* p) {
    const uint32_t u = *(const uint32_t*)p;
    return __half22float2(*(const __half2*)&u);
}

__global__ void scan_kernel(int mode, const int* __restrict__ sent_len,
                            float* __restrict__ out)
{
    const int tix = blockIdx.x * blockDim.x + threadIdx.x;
    if (tix >= (B_SZ * H_DIM) / 2) return;
    const int flat = tix * 2;
    const int b = flat / H_DIM;
    const int h = flat - b * H_DIM;       // even; H_DIM even -> no b straddle

    const size_t stride = (size_t)B_SZ * N3H;
    size_t base = (size_t)b * N3H + h;

    float2 c = make_float2(0.f, 0.f);

    if (mode != 2) {
        size_t xbase = (size_t)b * K2PAD + h;
        const size_t xstride = (size_t)B_SZ * K2PAD;
#pragma unroll 8
        for (int s = 0; s < S_LEN; ++s) {
            const float2 z = ld_gates2(g_gates + base);
            const float2 f = ld_gates2(g_gates + base + H_DIM);
            const float2 o = ld_gates2(g_gates + base + 2 * H_DIM);
            c.x = fmaf(f.x, c.x - z.x, z.x);
            c.y = fmaf(f.y, c.y - z.y, z.y);
            const __half2 hh = __floats2half2_rn(o.x * c.x, o.y * c.y);
            *(uint32_t*)(g_Ax + xbase) = *(const uint32_t*)&hh;
            base  += stride;
            xbase += xstride;
        }
    } else {
#pragma unroll 8
        for (int s = 0; s < S_LEN; ++s) {
            const float2 z = ld_gates2(g_gates + base);
            const float2 f = ld_gates2(g_gates + base + H_DIM);
            c.x = fmaf(f.x, c.x - z.x, z.x);
            c.y = fmaf(f.y, c.y - z.y, z.y);
            base += stride;
        }
    }

    if (mode == 0) {
        *(float2*)(g_acc + flat) = c;
    } else if (mode == 1) {
        float2 a = *(const float2*)(g_acc + flat);
        a.x += c.x; a.y += c.y;
        *(float2*)(g_acc + flat) = a;
    } else {
        const float inv = 1.0f / (float)sent_len[b];
        float2 a = *(const float2*)(g_acc + flat);
        float2 v;
        v.x = (a.x + c.x) * inv;
        v.y = (a.y + c.y) * inv;
        *(float2*)(out + flat) = v;
    }
}

// ---------------------------------------------------------------------------
extern "C" void kernel_launch(void* const* d_in, const int* in_sizes, int n_in,
                              void* d_out, int out_size)
{
    const float* sent     = (const float*)d_in[0];
    const int*   sent_len = (const int*)  d_in[1];
    const float* W1 = (const float*)d_in[2];
    const float* b1 = (const float*)d_in[3];
    const float* W2 = (const float*)d_in[4];
    const float* b2 = (const float*)d_in[5];
    const float* W3 = (const float*)d_in[6];
    const float* b3 = (const float*)d_in[7];
    float* out = (float*)d_out;

    cudaFuncSetAttribute(gemm_tc, cudaFuncAttributeMaxDynamicSharedMemorySize, GEMM_SMEM_BYTES);

    cvt_W_all<<<dim3(N3H, 3), 128>>>(W1, W2, W3);
    cvt_A1_kernel<<<M_ROWS, 64>>>(sent);

    const int nblocks = (M_ROWS / BM) * NGRP;             // 64 * 57 = 3648
    const int sblocks = ((B_SZ * H_DIM) / 2 + 127) / 128; // 300

    gemm_tc<<<nblocks, 256, GEMM_SMEM_BYTES>>>(1, b1);
    scan_kernel<<<sblocks, 128>>>(0, sent_len, out);

    gemm_tc<<<nblocks, 256, GEMM_SMEM_BYTES>>>(2, b2);
    scan_kernel<<<sblocks, 128>>>(1, sent_len, out);

    gemm_tc<<<nblocks, 256, GEMM_SMEM_BYTES>>>(3, b3);
    scan_kernel<<<sblocks, 128>>>(2, sent_len, out);
}

// round 11
// speedup vs baseline: 1.2399x; 1.0445x over previous
#include <cuda_runtime.h>
#include <cuda_fp16.h>
#include <math.h>
#include <stdint.h>

// ---------------------------------------------------------------------------
// Problem constants
// ---------------------------------------------------------------------------
#define S_LEN 256
#define B_SZ  32
#define E_DIM 300
#define H_DIM 2400
#define N3H   (3 * H_DIM)            // 7200
#define M_ROWS (S_LEN * B_SZ)        // 8192

#define K1PAD 320                    // 300 -> mult of 64
#define K2PAD 2432                   // 2400 -> mult of 64
#define NPAD  7296                   // 7200 -> mult of 128

#define BM 128
#define BN 128
#define BK 64
#define NSTAGE 3
#define NGRP (NPAD / BN)             // 57

// SMEM plane: 128 rows x 64 fp16 (128 B) padded to 144 B (conflict-free ldmatrix)
#define ROWB 144
#define PLANE_BYTES (128 * ROWB)     // 18432
#define OFF_A   0
#define OFF_B   PLANE_BYTES
#define STAGE_BYTES (2 * PLANE_BYTES)            // 36864
#define GEMM_SMEM_BYTES (NSTAGE * STAGE_BYTES)   // 110592 (x2 CTA = 221184 <= 228K)

// ---------------------------------------------------------------------------
// Scratch (__device__ globals: allocation-free; zero-initialized at load,
// so padded K/N regions read as 0)
// ---------------------------------------------------------------------------
__device__ __align__(16) __half g_A1[(size_t)M_ROWS * K1PAD];
__device__ __align__(16) __half g_Ax[(size_t)M_ROWS * K2PAD];
__device__ __align__(16) __half g_W1[(size_t)NPAD * K1PAD];
__device__ __align__(16) __half g_W2[(size_t)NPAD * K2PAD];
__device__ __align__(16) __half g_W3[(size_t)NPAD * K2PAD];
__device__ __align__(16) __half g_gates[(size_t)M_ROWS * N3H];   // fp16 gates
__device__ float g_acc[B_SZ * H_DIM];

// ---------------------------------------------------------------------------
__device__ __forceinline__ uint32_t smem_u32(const void* p) {
    uint32_t a;
    asm("{ .reg .u64 t; cvta.to.shared.u64 t, %1; cvt.u32.u64 %0, t; }" : "=r"(a) : "l"(p));
    return a;
}
__device__ __forceinline__ float sigmoid_f(float x) {
    return __fdividef(1.0f, 1.0f + __expf(-x));
}
__device__ __forceinline__ float tanh_fast(float x) {
    return 1.0f - __fdividef(2.0f, __expf(2.0f * x) + 1.0f);
}

#define CP_ASYNC16(dst, src) \
    asm volatile("cp.async.cg.shared.global [%0], [%1], 16;" :: "r"(dst), "l"(src) : "memory")
#define CP_COMMIT() asm volatile("cp.async.commit_group;" ::: "memory")
#define CP_WAIT(n)  asm volatile("cp.async.wait_group %0;" :: "n"(n) : "memory")

#define LDSM_X4(r0, r1, r2, r3, addr) \
    asm volatile("ldmatrix.sync.aligned.m8n8.x4.shared.b16 {%0,%1,%2,%3}, [%4];" \
                 : "=r"(r0), "=r"(r1), "=r"(r2), "=r"(r3) : "r"(addr))

#define MMA_FP16(d, a, b0, b1) \
    asm volatile("mma.sync.aligned.m16n8k16.row.col.f32.f16.f16.f32 " \
                 "{%0,%1,%2,%3}, {%4,%5,%6,%7}, {%8,%9}, {%0,%1,%2,%3};" \
                 : "+f"((d)[0]), "+f"((d)[1]), "+f"((d)[2]), "+f"((d)[3]) \
                 : "r"((a)[0]), "r"((a)[1]), "r"((a)[2]), "r"((a)[3]), "r"(b0), "r"(b1))

// ---------------------------------------------------------------------------
// fp32 -> fp16 conversions, vectorized. One launch covers all three W's.
// ---------------------------------------------------------------------------
__global__ void cvt_W_all(const float* __restrict__ w1in,
                          const float* __restrict__ w2in,
                          const float* __restrict__ w3in) {
    const int which = blockIdx.y;
    const float* in;
    __half* w;
    int K4, Kpad;
    if (which == 0)      { in = w1in; w = g_W1; K4 = E_DIM / 4; Kpad = K1PAD; }
    else if (which == 1) { in = w2in; w = g_W2; K4 = H_DIM / 4; Kpad = K2PAD; }
    else                 { in = w3in; w = g_W3; K4 = H_DIM / 4; Kpad = K2PAD; }
    const int r = blockIdx.x;
    const float4* row = (const float4*)(in + (size_t)r * (K4 * 4));
    for (int k4 = threadIdx.x; k4 < K4; k4 += blockDim.x) {
        const float4 x = row[k4];
        __half2 h01 = __floats2half2_rn(x.x, x.y);
        __half2 h23 = __floats2half2_rn(x.z, x.w);
        uint2 ph;
        ph.x = *(uint32_t*)&h01; ph.y = *(uint32_t*)&h23;
        *(uint2*)(w + (size_t)r * Kpad + k4 * 4) = ph;
    }
}

__global__ void cvt_A1_kernel(const float* __restrict__ sent) {
    const int r = blockIdx.x;
    const float4* row = (const float4*)(sent + (size_t)r * E_DIM);
    for (int k4 = threadIdx.x; k4 < E_DIM / 4; k4 += blockDim.x) {
        const float4 x = row[k4];
        __half2 h01 = __floats2half2_rn(x.x, x.y);
        __half2 h23 = __floats2half2_rn(x.z, x.w);
        uint2 ph;
        ph.x = *(uint32_t*)&h01; ph.y = *(uint32_t*)&h23;
        *(uint2*)(g_A1 + (size_t)r * K1PAD + k4 * 4) = ph;
    }
}

// ---------------------------------------------------------------------------
// fp16 HMMA GEMM (fp32 accum): g_gates[m,n] = act( A[m,:].W[n,:] + bias[n] )
// BM=128, BN=128, BK=64, warp tile 64x32, 3-stage pipeline, 2 CTAs/SM. (R8)
// ---------------------------------------------------------------------------
__global__ __launch_bounds__(256, 2) void gemm_tc(int layer, const float* __restrict__ bias) {
    const __half *A, *W;
    int Kpad;
    if (layer == 1)      { A = g_A1; W = g_W1; Kpad = K1PAD; }
    else if (layer == 2) { A = g_Ax; W = g_W2; Kpad = K2PAD; }
    else                 { A = g_Ax; W = g_W3; Kpad = K2PAD; }
    const int NT = Kpad / BK;

    // m-strip swizzle for L2 reuse: strips of 8 m-groups, n fastest
    const int bx = blockIdx.x;
    const int strip = bx / (8 * NGRP);
    const int rem   = bx % (8 * NGRP);
    const int mg    = strip * 8 + (rem % 8);
    const int ng    = rem / 8;
    const int m0 = mg * BM;
    const int n0 = ng * BN;

    extern __shared__ char smem_raw[];
    const uint32_t sbase = smem_u32(smem_raw);

    const int tid = threadIdx.x;
    const int wid = tid >> 5;
    const int lid = tid & 31;
    const int wm = (wid & 1) * 64;
    const int wn = (wid >> 1) * 32;

    auto load_chunk = [&](int t, int slot) {
        const uint32_t st = sbase + (uint32_t)slot * STAGE_BYTES;
        const int kc = t * BK;
#pragma unroll
        for (int i = 0; i < 4; i++) {
            const int u = tid + i * 256;
            const int r = u >> 3, c = u & 7;
            const uint32_t so = (uint32_t)(r * ROWB + c * 16);
            CP_ASYNC16(st + OFF_A + so, A + (size_t)(m0 + r) * Kpad + kc + c * 8);
            CP_ASYNC16(st + OFF_B + so, W + (size_t)(n0 + r) * Kpad + kc + c * 8);
        }
        CP_COMMIT();
    };

    float d[4][4][4];
#pragma unroll
    for (int mi = 0; mi < 4; mi++)
#pragma unroll
        for (int ni = 0; ni < 4; ni++)
#pragma unroll
            for (int q = 0; q < 4; q++) d[mi][ni][q] = 0.0f;

    const uint32_t a_row = (uint32_t)(wm + (lid & 15));
    const uint32_t a_kb  = (uint32_t)((lid >> 4) * 16);
    const uint32_t b_row = (uint32_t)(wn + (lid & 7) + ((lid >> 4) & 1) * 8);
    const uint32_t b_kb  = (uint32_t)(((lid >> 3) & 1) * 16);

    // Prologue: fill 2 of 3 stages
    load_chunk(0, 0);
    load_chunk(1, 1);

    for (int t = 0; t < NT; ++t) {
        CP_WAIT(1);            // chunk t landed (t+1 may still be in flight)
        __syncthreads();       // all warps done with slot being refilled

        if (t + 2 < NT) load_chunk(t + 2, (t + 2) % NSTAGE);
        else CP_COMMIT();      // keep outstanding-group count uniform

        const uint32_t st = sbase + (uint32_t)(t % NSTAGE) * STAGE_BYTES;
#pragma unroll
        for (int ks = 0; ks < 4; ks++) {
            const uint32_t kbyte = (uint32_t)(ks * 32);
            uint32_t af[4][4];
#pragma unroll
            for (int mi = 0; mi < 4; mi++) {
                const uint32_t ra = st + OFF_A + (a_row + mi * 16) * ROWB + kbyte + a_kb;
                LDSM_X4(af[mi][0], af[mi][1], af[mi][2], af[mi][3], ra);
            }
            uint32_t bf[4][2];
#pragma unroll
            for (int j = 0; j < 2; j++) {
                const uint32_t rb = st + OFF_B + (b_row + j * 16) * ROWB + kbyte + b_kb;
                LDSM_X4(bf[2*j][0], bf[2*j][1], bf[2*j+1][0], bf[2*j+1][1], rb);
            }
#pragma unroll
            for (int mi = 0; mi < 4; mi++)
#pragma unroll
                for (int ni = 0; ni < 4; ni++)
                    MMA_FP16(d[mi][ni], af[mi], bf[ni][0], bf[ni][1]);
        }
    }

    __syncthreads();

    // Epilogue: bias + activation + fp16 store
    const int er = lid >> 2;
    const int ec = (lid & 3) * 2;
#pragma unroll
    for (int mi = 0; mi < 4; mi++) {
#pragma unroll
        for (int ni = 0; ni < 4; ni++) {
            const int n = n0 + wn + ni * 8 + ec;     // even; H_DIM even -> no straddle
            if (n >= N3H) continue;
            const int m = m0 + wm + mi * 16 + er;
            const float2 bs = *(const float2*)(bias + n);
            const bool tA = (n < H_DIM);
            {
                const float y0 = d[mi][ni][0] + bs.x;
                const float y1 = d[mi][ni][1] + bs.y;
                const float v0 = tA ? tanh_fast(y0) : sigmoid_f(y0);
                const float v1 = tA ? tanh_fast(y1) : sigmoid_f(y1);
                *(__half2*)(g_gates + (size_t)m * N3H + n) = __floats2half2_rn(v0, v1);
            }
            {
                const float y0 = d[mi][ni][2] + bs.x;
                const float y1 = d[mi][ni][3] + bs.y;
                const float v0 = tA ? tanh_fast(y0) : sigmoid_f(y0);
                const float v1 = tA ? tanh_fast(y1) : sigmoid_f(y1);
                *(__half2*)(g_gates + (size_t)(m + 8) * N3H + n) = __floats2half2_rn(v0, v1);
            }
        }
    }
}

// ---------------------------------------------------------------------------
// fo-pool scan: 2 h-lanes/thread, depth-4 software-pipelined prefetch.
// Register FIFOs keep 12 loads/thread in flight (~3.7 MB chip-wide).
// ---------------------------------------------------------------------------
#define SD 4

__device__ __forceinline__ float2 ld_gates2(const __half* p) {
    const uint32_t u = *(const uint32_t*)p;
    return __half22float2(*(const __half2*)&u);
}

__global__ void scan_kernel(int mode, const int* __restrict__ sent_len,
                            float* __restrict__ out)
{
    const int tix = blockIdx.x * blockDim.x + threadIdx.x;
    if (tix >= (B_SZ * H_DIM) / 2) return;
    const int flat = tix * 2;
    const int b = flat / H_DIM;
    const int h = flat - b * H_DIM;       // even; H_DIM even -> no b straddle

    const size_t stride = (size_t)B_SZ * N3H;
    const __half* gp = g_gates + (size_t)b * N3H + h;

    float2 zb[SD], fb[SD], ob[SD];
    float2 c = make_float2(0.f, 0.f);

    if (mode != 2) {
        // Preload depth-SD window
#pragma unroll
        for (int i = 0; i < SD; i++) {
            const __half* q = gp + (size_t)i * stride;
            zb[i] = ld_gates2(q);
            fb[i] = ld_gates2(q + H_DIM);
            ob[i] = ld_gates2(q + 2 * H_DIM);
        }
        size_t xbase = (size_t)b * K2PAD + h;
        const size_t xstride = (size_t)B_SZ * K2PAD;
#pragma unroll 4
        for (int s = 0; s < S_LEN; ++s) {
            const int j = s & (SD - 1);
            const float2 z = zb[j], f = fb[j], o = ob[j];
            if (s + SD < S_LEN) {
                const __half* q = gp + (size_t)(s + SD) * stride;
                zb[j] = ld_gates2(q);
                fb[j] = ld_gates2(q + H_DIM);
                ob[j] = ld_gates2(q + 2 * H_DIM);
            }
            c.x = fmaf(f.x, c.x - z.x, z.x);
            c.y = fmaf(f.y, c.y - z.y, z.y);
            const __half2 hh = __floats2half2_rn(o.x * c.x, o.y * c.y);
            *(uint32_t*)(g_Ax + xbase) = *(const uint32_t*)&hh;
            xbase += xstride;
        }
    } else {
#pragma unroll
        for (int i = 0; i < SD; i++) {
            const __half* q = gp + (size_t)i * stride;
            zb[i] = ld_gates2(q);
            fb[i] = ld_gates2(q + H_DIM);
        }
#pragma unroll 4
        for (int s = 0; s < S_LEN; ++s) {
            const int j = s & (SD - 1);
            const float2 z = zb[j], f = fb[j];
            if (s + SD < S_LEN) {
                const __half* q = gp + (size_t)(s + SD) * stride;
                zb[j] = ld_gates2(q);
                fb[j] = ld_gates2(q + H_DIM);
            }
            c.x = fmaf(f.x, c.x - z.x, z.x);
            c.y = fmaf(f.y, c.y - z.y, z.y);
        }
    }

    if (mode == 0) {
        *(float2*)(g_acc + flat) = c;
    } else if (mode == 1) {
        float2 a = *(const float2*)(g_acc + flat);
        a.x += c.x; a.y += c.y;
        *(float2*)(g_acc + flat) = a;
    } else {
        const float inv = 1.0f / (float)sent_len[b];
        float2 a = *(const float2*)(g_acc + flat);
        float2 v;
        v.x = (a.x + c.x) * inv;
        v.y = (a.y + c.y) * inv;
        *(float2*)(out + flat) = v;
    }
}

// ---------------------------------------------------------------------------
extern "C" void kernel_launch(void* const* d_in, const int* in_sizes, int n_in,
                              void* d_out, int out_size)
{
    const float* sent     = (const float*)d_in[0];
    const int*   sent_len = (const int*)  d_in[1];
    const float* W1 = (const float*)d_in[2];
    const float* b1 = (const float*)d_in[3];
    const float* W2 = (const float*)d_in[4];
    const float* b2 = (const float*)d_in[5];
    const float* W3 = (const float*)d_in[6];
    const float* b3 = (const float*)d_in[7];
    float* out = (float*)d_out;

    cudaFuncSetAttribute(gemm_tc, cudaFuncAttributeMaxDynamicSharedMemorySize, GEMM_SMEM_BYTES);

    cvt_W_all<<<dim3(N3H, 3), 128>>>(W1, W2, W3);
    cvt_A1_kernel<<<M_ROWS, 64>>>(sent);

    const int nblocks = (M_ROWS / BM) * NGRP;             // 64 * 57 = 3648
    const int sblocks = ((B_SZ * H_DIM) / 2 + 127) / 128; // 300

    gemm_tc<<<nblocks, 256, GEMM_SMEM_BYTES>>>(1, b1);
    scan_kernel<<<sblocks, 128>>>(0, sent_len, out);

    gemm_tc<<<nblocks, 256, GEMM_SMEM_BYTES>>>(2, b2);
    scan_kernel<<<sblocks, 128>>>(1, sent_len, out);

    gemm_tc<<<nblocks, 256, GEMM_SMEM_BYTES>>>(3, b3);
    scan_kernel<<<sblocks, 128>>>(2, sent_len, out);
}

// round 12
// speedup vs baseline: 1.3075x; 1.0545x over previous
#include <cuda_runtime.h>
#include <cuda_fp16.h>
#include <math.h>
#include <stdint.h>

// ---------------------------------------------------------------------------
// Problem constants
// ---------------------------------------------------------------------------
#define S_LEN 256
#define B_SZ  32
#define E_DIM 300
#define H_DIM 2400
#define N3H   (3 * H_DIM)            // 7200
#define M_ROWS (S_LEN * B_SZ)        // 8192

#define K1PAD 320                    // 300 -> mult of 64
#define K2PAD 2432                   // 2400 -> mult of 64
#define NPAD  7296                   // 7200 -> mult of 128

#define BM 128
#define BN 128
#define BK 64
#define NSTAGE 3
#define NGRP (NPAD / BN)             // 57

// SMEM plane: 128 rows x 64 fp16 (128 B) padded to 144 B (conflict-free ldmatrix)
#define ROWB 144
#define PLANE_BYTES (128 * ROWB)     // 18432
#define OFF_A   0
#define OFF_B   PLANE_BYTES
#define STAGE_BYTES (2 * PLANE_BYTES)            // 36864
#define GEMM_SMEM_BYTES (NSTAGE * STAGE_BYTES)   // 110592 (x2 CTA = 221184 <= 228K)

// ---------------------------------------------------------------------------
// Scratch (__device__ globals: allocation-free; zero-initialized at load,
// so padded K/N regions read as 0)
// ---------------------------------------------------------------------------
__device__ __align__(16) __half g_A1[(size_t)M_ROWS * K1PAD];
__device__ __align__(16) __half g_Ax[(size_t)M_ROWS * K2PAD];
__device__ __align__(16) __half g_W1[(size_t)NPAD * K1PAD];
__device__ __align__(16) __half g_W2[(size_t)NPAD * K2PAD];
__device__ __align__(16) __half g_W3[(size_t)NPAD * K2PAD];
__device__ __align__(16) __half g_gates[(size_t)M_ROWS * N3H];   // fp16 gates
__device__ float g_acc[B_SZ * H_DIM];

// ---------------------------------------------------------------------------
__device__ __forceinline__ uint32_t smem_u32(const void* p) {
    uint32_t a;
    asm("{ .reg .u64 t; cvta.to.shared.u64 t, %1; cvt.u32.u64 %0, t; }" : "=r"(a) : "l"(p));
    return a;
}
__device__ __forceinline__ float sigmoid_f(float x) {
    return __fdividef(1.0f, 1.0f + __expf(-x));
}
__device__ __forceinline__ float tanh_fast(float x) {
    return 1.0f - __fdividef(2.0f, __expf(2.0f * x) + 1.0f);
}

#define CP_ASYNC16(dst, src) \
    asm volatile("cp.async.cg.shared.global [%0], [%1], 16;" :: "r"(dst), "l"(src) : "memory")
#define CP_COMMIT() asm volatile("cp.async.commit_group;" ::: "memory")
#define CP_WAIT(n)  asm volatile("cp.async.wait_group %0;" :: "n"(n) : "memory")

#define LDSM_X4(r0, r1, r2, r3, addr) \
    asm volatile("ldmatrix.sync.aligned.m8n8.x4.shared.b16 {%0,%1,%2,%3}, [%4];" \
                 : "=r"(r0), "=r"(r1), "=r"(r2), "=r"(r3) : "r"(addr))

#define MMA_FP16(d, a, b0, b1) \
    asm volatile("mma.sync.aligned.m16n8k16.row.col.f32.f16.f16.f32 " \
                 "{%0,%1,%2,%3}, {%4,%5,%6,%7}, {%8,%9}, {%0,%1,%2,%3};" \
                 : "+f"((d)[0]), "+f"((d)[1]), "+f"((d)[2]), "+f"((d)[3]) \
                 : "r"((a)[0]), "r"((a)[1]), "r"((a)[2]), "r"((a)[3]), "r"(b0), "r"(b1))

// ---------------------------------------------------------------------------
// fp32 -> fp16 conversions, vectorized. One launch covers all three W's.
// ---------------------------------------------------------------------------
__global__ void cvt_W_all(const float* __restrict__ w1in,
                          const float* __restrict__ w2in,
                          const float* __restrict__ w3in) {
    const int which = blockIdx.y;
    const float* in;
    __half* w;
    int K4, Kpad;
    if (which == 0)      { in = w1in; w = g_W1; K4 = E_DIM / 4; Kpad = K1PAD; }
    else if (which == 1) { in = w2in; w = g_W2; K4 = H_DIM / 4; Kpad = K2PAD; }
    else                 { in = w3in; w = g_W3; K4 = H_DIM / 4; Kpad = K2PAD; }
    const int r = blockIdx.x;
    const float4* row = (const float4*)(in + (size_t)r * (K4 * 4));
    for (int k4 = threadIdx.x; k4 < K4; k4 += blockDim.x) {
        const float4 x = row[k4];
        __half2 h01 = __floats2half2_rn(x.x, x.y);
        __half2 h23 = __floats2half2_rn(x.z, x.w);
        uint2 ph;
        ph.x = *(uint32_t*)&h01; ph.y = *(uint32_t*)&h23;
        *(uint2*)(w + (size_t)r * Kpad + k4 * 4) = ph;
    }
}

__global__ void cvt_A1_kernel(const float* __restrict__ sent) {
    const int r = blockIdx.x;
    const float4* row = (const float4*)(sent + (size_t)r * E_DIM);
    for (int k4 = threadIdx.x; k4 < E_DIM / 4; k4 += blockDim.x) {
        const float4 x = row[k4];
        __half2 h01 = __floats2half2_rn(x.x, x.y);
        __half2 h23 = __floats2half2_rn(x.z, x.w);
        uint2 ph;
        ph.x = *(uint32_t*)&h01; ph.y = *(uint32_t*)&h23;
        *(uint2*)(g_A1 + (size_t)r * K1PAD + k4 * 4) = ph;
    }
}

// ---------------------------------------------------------------------------
// fp16 HMMA GEMM (fp32 accum): g_gates[m,n] = act( A[m,:].W[n,:] + bias[n] )
// BM=128, BN=128, BK=64, warp tile 64x32, 3-stage pipeline, 2 CTAs/SM. (R8)
// ---------------------------------------------------------------------------
__global__ __launch_bounds__(256, 2) void gemm_tc(int layer, const float* __restrict__ bias) {
    const __half *A, *W;
    int Kpad;
    if (layer == 1)      { A = g_A1; W = g_W1; Kpad = K1PAD; }
    else if (layer == 2) { A = g_Ax; W = g_W2; Kpad = K2PAD; }
    else                 { A = g_Ax; W = g_W3; Kpad = K2PAD; }
    const int NT = Kpad / BK;

    // m-strip swizzle for L2 reuse: strips of 8 m-groups, n fastest
    const int bx = blockIdx.x;
    const int strip = bx / (8 * NGRP);
    const int rem   = bx % (8 * NGRP);
    const int mg    = strip * 8 + (rem % 8);
    const int ng    = rem / 8;
    const int m0 = mg * BM;
    const int n0 = ng * BN;

    extern __shared__ char smem_raw[];
    const uint32_t sbase = smem_u32(smem_raw);

    const int tid = threadIdx.x;
    const int wid = tid >> 5;
    const int lid = tid & 31;
    const int wm = (wid & 1) * 64;
    const int wn = (wid >> 1) * 32;

    auto load_chunk = [&](int t, int slot) {
        const uint32_t st = sbase + (uint32_t)slot * STAGE_BYTES;
        const int kc = t * BK;
#pragma unroll
        for (int i = 0; i < 4; i++) {
            const int u = tid + i * 256;
            const int r = u >> 3, c = u & 7;
            const uint32_t so = (uint32_t)(r * ROWB + c * 16);
            CP_ASYNC16(st + OFF_A + so, A + (size_t)(m0 + r) * Kpad + kc + c * 8);
            CP_ASYNC16(st + OFF_B + so, W + (size_t)(n0 + r) * Kpad + kc + c * 8);
        }
        CP_COMMIT();
    };

    float d[4][4][4];
#pragma unroll
    for (int mi = 0; mi < 4; mi++)
#pragma unroll
        for (int ni = 0; ni < 4; ni++)
#pragma unroll
            for (int q = 0; q < 4; q++) d[mi][ni][q] = 0.0f;

    const uint32_t a_row = (uint32_t)(wm + (lid & 15));
    const uint32_t a_kb  = (uint32_t)((lid >> 4) * 16);
    const uint32_t b_row = (uint32_t)(wn + (lid & 7) + ((lid >> 4) & 1) * 8);
    const uint32_t b_kb  = (uint32_t)(((lid >> 3) & 1) * 16);

    // Prologue: fill 2 of 3 stages
    load_chunk(0, 0);
    load_chunk(1, 1);

    for (int t = 0; t < NT; ++t) {
        CP_WAIT(1);            // chunk t landed (t+1 may still be in flight)
        __syncthreads();       // all warps done with slot being refilled

        if (t + 2 < NT) load_chunk(t + 2, (t + 2) % NSTAGE);
        else CP_COMMIT();      // keep outstanding-group count uniform

        const uint32_t st = sbase + (uint32_t)(t % NSTAGE) * STAGE_BYTES;
#pragma unroll
        for (int ks = 0; ks < 4; ks++) {
            const uint32_t kbyte = (uint32_t)(ks * 32);
            uint32_t af[4][4];
#pragma unroll
            for (int mi = 0; mi < 4; mi++) {
                const uint32_t ra = st + OFF_A + (a_row + mi * 16) * ROWB + kbyte + a_kb;
                LDSM_X4(af[mi][0], af[mi][1], af[mi][2], af[mi][3], ra);
            }
            uint32_t bf[4][2];
#pragma unroll
            for (int j = 0; j < 2; j++) {
                const uint32_t rb = st + OFF_B + (b_row + j * 16) * ROWB + kbyte + b_kb;
                LDSM_X4(bf[2*j][0], bf[2*j][1], bf[2*j+1][0], bf[2*j+1][1], rb);
            }
#pragma unroll
            for (int mi = 0; mi < 4; mi++)
#pragma unroll
                for (int ni = 0; ni < 4; ni++)
                    MMA_FP16(d[mi][ni], af[mi], bf[ni][0], bf[ni][1]);
        }
    }

    __syncthreads();

    // Epilogue: bias + activation + fp16 store
    const int er = lid >> 2;
    const int ec = (lid & 3) * 2;
#pragma unroll
    for (int mi = 0; mi < 4; mi++) {
#pragma unroll
        for (int ni = 0; ni < 4; ni++) {
            const int n = n0 + wn + ni * 8 + ec;     // even; H_DIM even -> no straddle
            if (n >= N3H) continue;
            const int m = m0 + wm + mi * 16 + er;
            const float2 bs = *(const float2*)(bias + n);
            const bool tA = (n < H_DIM);
            {
                const float y0 = d[mi][ni][0] + bs.x;
                const float y1 = d[mi][ni][1] + bs.y;
                const float v0 = tA ? tanh_fast(y0) : sigmoid_f(y0);
                const float v1 = tA ? tanh_fast(y1) : sigmoid_f(y1);
                *(__half2*)(g_gates + (size_t)m * N3H + n) = __floats2half2_rn(v0, v1);
            }
            {
                const float y0 = d[mi][ni][2] + bs.x;
                const float y1 = d[mi][ni][3] + bs.y;
                const float v0 = tA ? tanh_fast(y0) : sigmoid_f(y0);
                const float v1 = tA ? tanh_fast(y1) : sigmoid_f(y1);
                *(__half2*)(g_gates + (size_t)(m + 8) * N3H + n) = __floats2half2_rn(v0, v1);
            }
        }
    }
}

// ---------------------------------------------------------------------------
// fo-pool scan: 2 h-lanes/thread, depth-8 software-pipelined prefetch.
// Register FIFOs keep 24 loads/thread in flight (~7.4 MB chip-wide).
// ---------------------------------------------------------------------------
#define SD 8

__device__ __forceinline__ float2 ld_gates2(const __half* p) {
    const uint32_t u = *(const uint32_t*)p;
    return __half22float2(*(const __half2*)&u);
}

__global__ void scan_kernel(int mode, const int* __restrict__ sent_len,
                            float* __restrict__ out)
{
    const int tix = blockIdx.x * blockDim.x + threadIdx.x;
    if (tix >= (B_SZ * H_DIM) / 2) return;
    const int flat = tix * 2;
    const int b = flat / H_DIM;
    const int h = flat - b * H_DIM;       // even; H_DIM even -> no b straddle

    const size_t stride = (size_t)B_SZ * N3H;
    const __half* gp = g_gates + (size_t)b * N3H + h;

    float2 zb[SD], fb[SD], ob[SD];
    float2 c = make_float2(0.f, 0.f);

    if (mode != 2) {
        // Preload depth-SD window
#pragma unroll
        for (int i = 0; i < SD; i++) {
            const __half* q = gp + (size_t)i * stride;
            zb[i] = ld_gates2(q);
            fb[i] = ld_gates2(q + H_DIM);
            ob[i] = ld_gates2(q + 2 * H_DIM);
        }
        size_t xbase = (size_t)b * K2PAD + h;
        const size_t xstride = (size_t)B_SZ * K2PAD;
#pragma unroll 8
        for (int s = 0; s < S_LEN; ++s) {
            const int j = s & (SD - 1);
            const float2 z = zb[j], f = fb[j], o = ob[j];
            if (s + SD < S_LEN) {
                const __half* q = gp + (size_t)(s + SD) * stride;
                zb[j] = ld_gates2(q);
                fb[j] = ld_gates2(q + H_DIM);
                ob[j] = ld_gates2(q + 2 * H_DIM);
            }
            c.x = fmaf(f.x, c.x - z.x, z.x);
            c.y = fmaf(f.y, c.y - z.y, z.y);
            const __half2 hh = __floats2half2_rn(o.x * c.x, o.y * c.y);
            *(uint32_t*)(g_Ax + xbase) = *(const uint32_t*)&hh;
            xbase += xstride;
        }
    } else {
#pragma unroll
        for (int i = 0; i < SD; i++) {
            const __half* q = gp + (size_t)i * stride;
            zb[i] = ld_gates2(q);
            fb[i] = ld_gates2(q + H_DIM);
        }
#pragma unroll 8
        for (int s = 0; s < S_LEN; ++s) {
            const int j = s & (SD - 1);
            const float2 z = zb[j], f = fb[j];
            if (s + SD < S_LEN) {
                const __half* q = gp + (size_t)(s + SD) * stride;
                zb[j] = ld_gates2(q);
                fb[j] = ld_gates2(q + H_DIM);
            }
            c.x = fmaf(f.x, c.x - z.x, z.x);
            c.y = fmaf(f.y, c.y - z.y, z.y);
        }
    }

    if (mode == 0) {
        *(float2*)(g_acc + flat) = c;
    } else if (mode == 1) {
        float2 a = *(const float2*)(g_acc + flat);
        a.x += c.x; a.y += c.y;
        *(float2*)(g_acc + flat) = a;
    } else {
        const float inv = 1.0f / (float)sent_len[b];
        float2 a = *(const float2*)(g_acc + flat);
        float2 v;
        v.x = (a.x + c.x) * inv;
        v.y = (a.y + c.y) * inv;
        *(float2*)(out + flat) = v;
    }
}

// ---------------------------------------------------------------------------
extern "C" void kernel_launch(void* const* d_in, const int* in_sizes, int n_in,
                              void* d_out, int out_size)
{
    const float* sent     = (const float*)d_in[0];
    const int*   sent_len = (const int*)  d_in[1];
    const float* W1 = (const float*)d_in[2];
    const float* b1 = (const float*)d_in[3];
    const float* W2 = (const float*)d_in[4];
    const float* b2 = (const float*)d_in[5];
    const float* W3 = (const float*)d_in[6];
    const float* b3 = (const float*)d_in[7];
    float* out = (float*)d_out;

    cudaFuncSetAttribute(gemm_tc, cudaFuncAttributeMaxDynamicSharedMemorySize, GEMM_SMEM_BYTES);

    cvt_W_all<<<dim3(N3H, 3), 128>>>(W1, W2, W3);
    cvt_A1_kernel<<<M_ROWS, 64>>>(sent);

    const int nblocks = (M_ROWS / BM) * NGRP;             // 64 * 57 = 3648
    const int sblocks = ((B_SZ * H_DIM) / 2 + 127) / 128; // 300

    gemm_tc<<<nblocks, 256, GEMM_SMEM_BYTES>>>(1, b1);
    scan_kernel<<<sblocks, 128>>>(0, sent_len, out);

    gemm_tc<<<nblocks, 256, GEMM_SMEM_BYTES>>>(2, b2);
    scan_kernel<<<sblocks, 128>>>(1, sent_len, out);

    gemm_tc<<<nblocks, 256, GEMM_SMEM_BYTES>>>(3, b3);
    scan_kernel<<<sblocks, 128>>>(2, sent_len, out);
}

// round 13
// speedup vs baseline: 1.3605x; 1.0405x over previous
#include <cuda_runtime.h>
#include <cuda_fp16.h>
#include <math.h>
#include <stdint.h>

// ---------------------------------------------------------------------------
// Problem constants
// ---------------------------------------------------------------------------
#define S_LEN 256
#define B_SZ  32
#define E_DIM 300
#define H_DIM 2400
#define N3H   (3 * H_DIM)            // 7200
#define M_ROWS (S_LEN * B_SZ)        // 8192

#define K1PAD 320                    // 300 -> mult of 64
#define K2PAD 2432                   // 2400 -> mult of 64
#define NPAD  7296                   // 7200 -> mult of 128

#define BM 128
#define BN 128
#define BK 64
#define NSTAGE 3
#define NGRP_FULL 57                 // ceil(7200/128): layers 1,2
#define NGRP_L3   38                 // ceil(4800/128): layer 3 (O-gate unused)

// SMEM plane: 128 rows x 64 fp16 (128 B) padded to 144 B (conflict-free ldmatrix)
#define ROWB 144
#define PLANE_BYTES (128 * ROWB)     // 18432
#define OFF_A   0
#define OFF_B   PLANE_BYTES
#define STAGE_BYTES (2 * PLANE_BYTES)            // 36864
#define GEMM_SMEM_BYTES (NSTAGE * STAGE_BYTES)   // 110592 (x2 CTA = 221184 <= 228K)

// ---------------------------------------------------------------------------
// Scratch (__device__ globals: allocation-free; zero-initialized at load,
// so padded K/N regions read as 0)
// ---------------------------------------------------------------------------
__device__ __align__(16) __half g_A1[(size_t)M_ROWS * K1PAD];
__device__ __align__(16) __half g_Ax[(size_t)M_ROWS * K2PAD];
__device__ __align__(16) __half g_W1[(size_t)NPAD * K1PAD];
__device__ __align__(16) __half g_W2[(size_t)NPAD * K2PAD];
__device__ __align__(16) __half g_W3[(size_t)NPAD * K2PAD];
__device__ __align__(16) __half g_gates[(size_t)M_ROWS * N3H];   // fp16 gates
__device__ float g_acc[B_SZ * H_DIM];

// ---------------------------------------------------------------------------
__device__ __forceinline__ uint32_t smem_u32(const void* p) {
    uint32_t a;
    asm("{ .reg .u64 t; cvta.to.shared.u64 t, %1; cvt.u32.u64 %0, t; }" : "=r"(a) : "l"(p));
    return a;
}
__device__ __forceinline__ float sigmoid_f(float x) {
    return __fdividef(1.0f, 1.0f + __expf(-x));
}
__device__ __forceinline__ float tanh_fast(float x) {
    return 1.0f - __fdividef(2.0f, __expf(2.0f * x) + 1.0f);
}

#define CP_ASYNC16(dst, src) \
    asm volatile("cp.async.cg.shared.global [%0], [%1], 16;" :: "r"(dst), "l"(src) : "memory")
#define CP_COMMIT() asm volatile("cp.async.commit_group;" ::: "memory")
#define CP_WAIT(n)  asm volatile("cp.async.wait_group %0;" :: "n"(n) : "memory")

#define LDSM_X4(r0, r1, r2, r3, addr) \
    asm volatile("ldmatrix.sync.aligned.m8n8.x4.shared.b16 {%0,%1,%2,%3}, [%4];" \
                 : "=r"(r0), "=r"(r1), "=r"(r2), "=r"(r3) : "r"(addr))

#define MMA_FP16(d, a, b0, b1) \
    asm volatile("mma.sync.aligned.m16n8k16.row.col.f32.f16.f16.f32 " \
                 "{%0,%1,%2,%3}, {%4,%5,%6,%7}, {%8,%9}, {%0,%1,%2,%3};" \
                 : "+f"((d)[0]), "+f"((d)[1]), "+f"((d)[2]), "+f"((d)[3]) \
                 : "r"((a)[0]), "r"((a)[1]), "r"((a)[2]), "r"((a)[3]), "r"(b0), "r"(b1))

// ---------------------------------------------------------------------------
// fp32 -> fp16 conversions, vectorized. One launch covers all three W's.
// ---------------------------------------------------------------------------
__global__ void cvt_W_all(const float* __restrict__ w1in,
                          const float* __restrict__ w2in,
                          const float* __restrict__ w3in) {
    const int which = blockIdx.y;
    const float* in;
    __half* w;
    int K4, Kpad;
    if (which == 0)      { in = w1in; w = g_W1; K4 = E_DIM / 4; Kpad = K1PAD; }
    else if (which == 1) { in = w2in; w = g_W2; K4 = H_DIM / 4; Kpad = K2PAD; }
    else                 { in = w3in; w = g_W3; K4 = H_DIM / 4; Kpad = K2PAD; }
    const int r = blockIdx.x;
    const float4* row = (const float4*)(in + (size_t)r * (K4 * 4));
    for (int k4 = threadIdx.x; k4 < K4; k4 += blockDim.x) {
        const float4 x = row[k4];
        __half2 h01 = __floats2half2_rn(x.x, x.y);
        __half2 h23 = __floats2half2_rn(x.z, x.w);
        uint2 ph;
        ph.x = *(uint32_t*)&h01; ph.y = *(uint32_t*)&h23;
        *(uint2*)(w + (size_t)r * Kpad + k4 * 4) = ph;
    }
}

__global__ void cvt_A1_kernel(const float* __restrict__ sent) {
    const int r = blockIdx.x;
    const float4* row = (const float4*)(sent + (size_t)r * E_DIM);
    for (int k4 = threadIdx.x; k4 < E_DIM / 4; k4 += blockDim.x) {
        const float4 x = row[k4];
        __half2 h01 = __floats2half2_rn(x.x, x.y);
        __half2 h23 = __floats2half2_rn(x.z, x.w);
        uint2 ph;
        ph.x = *(uint32_t*)&h01; ph.y = *(uint32_t*)&h23;
        *(uint2*)(g_A1 + (size_t)r * K1PAD + k4 * 4) = ph;
    }
}

// ---------------------------------------------------------------------------
// fp16 HMMA GEMM (fp32 accum): g_gates[m,n] = act( A[m,:].W[n,:] + bias[n] )
// BM=128, BN=128, BK=64, warp tile 64x32, 3-stage pipeline, 2 CTAs/SM.
// ngrp parametrizes the n-extent (layer 3 skips the unused O-gate columns).
// ---------------------------------------------------------------------------
__global__ __launch_bounds__(256, 2) void gemm_tc(int layer, const float* __restrict__ bias,
                                                  int ngrp) {
    const __half *A, *W;
    int Kpad;
    if (layer == 1)      { A = g_A1; W = g_W1; Kpad = K1PAD; }
    else if (layer == 2) { A = g_Ax; W = g_W2; Kpad = K2PAD; }
    else                 { A = g_Ax; W = g_W3; Kpad = K2PAD; }
    const int NT = Kpad / BK;

    // m-strip swizzle for L2 reuse: strips of 8 m-groups, n fastest
    const int bx = blockIdx.x;
    const int strip = bx / (8 * ngrp);
    const int rem   = bx % (8 * ngrp);
    const int mg    = strip * 8 + (rem % 8);
    const int ng    = rem / 8;
    const int m0 = mg * BM;
    const int n0 = ng * BN;

    extern __shared__ char smem_raw[];
    const uint32_t sbase = smem_u32(smem_raw);

    const int tid = threadIdx.x;
    const int wid = tid >> 5;
    const int lid = tid & 31;
    const int wm = (wid & 1) * 64;
    const int wn = (wid >> 1) * 32;

    auto load_chunk = [&](int t, int slot) {
        const uint32_t st = sbase + (uint32_t)slot * STAGE_BYTES;
        const int kc = t * BK;
#pragma unroll
        for (int i = 0; i < 4; i++) {
            const int u = tid + i * 256;
            const int r = u >> 3, c = u & 7;
            const uint32_t so = (uint32_t)(r * ROWB + c * 16);
            CP_ASYNC16(st + OFF_A + so, A + (size_t)(m0 + r) * Kpad + kc + c * 8);
            CP_ASYNC16(st + OFF_B + so, W + (size_t)(n0 + r) * Kpad + kc + c * 8);
        }
        CP_COMMIT();
    };

    float d[4][4][4];
#pragma unroll
    for (int mi = 0; mi < 4; mi++)
#pragma unroll
        for (int ni = 0; ni < 4; ni++)
#pragma unroll
            for (int q = 0; q < 4; q++) d[mi][ni][q] = 0.0f;

    const uint32_t a_row = (uint32_t)(wm + (lid & 15));
    const uint32_t a_kb  = (uint32_t)((lid >> 4) * 16);
    const uint32_t b_row = (uint32_t)(wn + (lid & 7) + ((lid >> 4) & 1) * 8);
    const uint32_t b_kb  = (uint32_t)(((lid >> 3) & 1) * 16);

    // Prologue: fill 2 of 3 stages
    load_chunk(0, 0);
    load_chunk(1, 1);

    for (int t = 0; t < NT; ++t) {
        CP_WAIT(1);            // chunk t landed (t+1 may still be in flight)
        __syncthreads();       // all warps done with slot being refilled

        if (t + 2 < NT) load_chunk(t + 2, (t + 2) % NSTAGE);
        else CP_COMMIT();      // keep outstanding-group count uniform

        const uint32_t st = sbase + (uint32_t)(t % NSTAGE) * STAGE_BYTES;
#pragma unroll
        for (int ks = 0; ks < 4; ks++) {
            const uint32_t kbyte = (uint32_t)(ks * 32);
            uint32_t af[4][4];
#pragma unroll
            for (int mi = 0; mi < 4; mi++) {
                const uint32_t ra = st + OFF_A + (a_row + mi * 16) * ROWB + kbyte + a_kb;
                LDSM_X4(af[mi][0], af[mi][1], af[mi][2], af[mi][3], ra);
            }
            uint32_t bf[4][2];
#pragma unroll
            for (int j = 0; j < 2; j++) {
                const uint32_t rb = st + OFF_B + (b_row + j * 16) * ROWB + kbyte + b_kb;
                LDSM_X4(bf[2*j][0], bf[2*j][1], bf[2*j+1][0], bf[2*j+1][1], rb);
            }
#pragma unroll
            for (int mi = 0; mi < 4; mi++)
#pragma unroll
                for (int ni = 0; ni < 4; ni++)
                    MMA_FP16(d[mi][ni], af[mi], bf[ni][0], bf[ni][1]);
        }
    }

    __syncthreads();

    // Epilogue: bias + activation + fp16 store
    const int er = lid >> 2;
    const int ec = (lid & 3) * 2;
#pragma unroll
    for (int mi = 0; mi < 4; mi++) {
#pragma unroll
        for (int ni = 0; ni < 4; ni++) {
            const int n = n0 + wn + ni * 8 + ec;     // even; H_DIM even -> no straddle
            if (n >= N3H) continue;
            const int m = m0 + wm + mi * 16 + er;
            const float2 bs = *(const float2*)(bias + n);
            const bool tA = (n < H_DIM);
            {
                const float y0 = d[mi][ni][0] + bs.x;
                const float y1 = d[mi][ni][1] + bs.y;
                const float v0 = tA ? tanh_fast(y0) : sigmoid_f(y0);
                const float v1 = tA ? tanh_fast(y1) : sigmoid_f(y1);
                *(__half2*)(g_gates + (size_t)m * N3H + n) = __floats2half2_rn(v0, v1);
            }
            {
                const float y0 = d[mi][ni][2] + bs.x;
                const float y1 = d[mi][ni][3] + bs.y;
                const float v0 = tA ? tanh_fast(y0) : sigmoid_f(y0);
                const float v1 = tA ? tanh_fast(y1) : sigmoid_f(y1);
                *(__half2*)(g_gates + (size_t)(m + 8) * N3H + n) = __floats2half2_rn(v0, v1);
            }
        }
    }
}

// ---------------------------------------------------------------------------
// fo-pool scan: 2 h-lanes/thread, depth-16 software-pipelined prefetch.
// ---------------------------------------------------------------------------
#define SD 16

__device__ __forceinline__ float2 ld_gates2(const __half* p) {
    const uint32_t u = *(const uint32_t*)p;
    return __half22float2(*(const __half2*)&u);
}

__global__ void scan_kernel(int mode, const int* __restrict__ sent_len,
                            float* __restrict__ out)
{
    const int tix = blockIdx.x * blockDim.x + threadIdx.x;
    if (tix >= (B_SZ * H_DIM) / 2) return;
    const int flat = tix * 2;
    const int b = flat / H_DIM;
    const int h = flat - b * H_DIM;       // even; H_DIM even -> no b straddle

    const size_t stride = (size_t)B_SZ * N3H;
    const __half* gp = g_gates + (size_t)b * N3H + h;

    float2 c = make_float2(0.f, 0.f);

    if (mode != 2) {
        float2 zb[SD], fb[SD], ob[SD];
#pragma unroll
        for (int i = 0; i < SD; i++) {
            const __half* q = gp + (size_t)i * stride;
            zb[i] = ld_gates2(q);
            fb[i] = ld_gates2(q + H_DIM);
            ob[i] = ld_gates2(q + 2 * H_DIM);
        }
        size_t xbase = (size_t)b * K2PAD + h;
        const size_t xstride = (size_t)B_SZ * K2PAD;
#pragma unroll 16
        for (int s = 0; s < S_LEN; ++s) {
            const int j = s & (SD - 1);
            const float2 z = zb[j], f = fb[j], o = ob[j];
            if (s + SD < S_LEN) {
                const __half* q = gp + (size_t)(s + SD) * stride;
                zb[j] = ld_gates2(q);
                fb[j] = ld_gates2(q + H_DIM);
                ob[j] = ld_gates2(q + 2 * H_DIM);
            }
            c.x = fmaf(f.x, c.x - z.x, z.x);
            c.y = fmaf(f.y, c.y - z.y, z.y);
            const __half2 hh = __floats2half2_rn(o.x * c.x, o.y * c.y);
            *(uint32_t*)(g_Ax + xbase) = *(const uint32_t*)&hh;
            xbase += xstride;
        }
    } else {
        float2 zb[SD], fb[SD];
#pragma unroll
        for (int i = 0; i < SD; i++) {
            const __half* q = gp + (size_t)i * stride;
            zb[i] = ld_gates2(q);
            fb[i] = ld_gates2(q + H_DIM);
        }
#pragma unroll 16
        for (int s = 0; s < S_LEN; ++s) {
            const int j = s & (SD - 1);
            const float2 z = zb[j], f = fb[j];
            if (s + SD < S_LEN) {
                const __half* q = gp + (size_t)(s + SD) * stride;
                zb[j] = ld_gates2(q);
                fb[j] = ld_gates2(q + H_DIM);
            }
            c.x = fmaf(f.x, c.x - z.x, z.x);
            c.y = fmaf(f.y, c.y - z.y, z.y);
        }
    }

    if (mode == 0) {
        *(float2*)(g_acc + flat) = c;
    } else if (mode == 1) {
        float2 a = *(const float2*)(g_acc + flat);
        a.x += c.x; a.y += c.y;
        *(float2*)(g_acc + flat) = a;
    } else {
        const float inv = 1.0f / (float)sent_len[b];
        float2 a = *(const float2*)(g_acc + flat);
        float2 v;
        v.x = (a.x + c.x) * inv;
        v.y = (a.y + c.y) * inv;
        *(float2*)(out + flat) = v;
    }
}

// ---------------------------------------------------------------------------
extern "C" void kernel_launch(void* const* d_in, const int* in_sizes, int n_in,
                              void* d_out, int out_size)
{
    const float* sent     = (const float*)d_in[0];
    const int*   sent_len = (const int*)  d_in[1];
    const float* W1 = (const float*)d_in[2];
    const float* b1 = (const float*)d_in[3];
    const float* W2 = (const float*)d_in[4];
    const float* b2 = (const float*)d_in[5];
    const float* W3 = (const float*)d_in[6];
    const float* b3 = (const float*)d_in[7];
    float* out = (float*)d_out;

    cudaFuncSetAttribute(gemm_tc, cudaFuncAttributeMaxDynamicSharedMemorySize, GEMM_SMEM_BYTES);

    cvt_W_all<<<dim3(N3H, 3), 128>>>(W1, W2, W3);
    cvt_A1_kernel<<<M_ROWS, 64>>>(sent);

    const int nblocks_full = (M_ROWS / BM) * NGRP_FULL;   // 64 * 57 = 3648
    const int nblocks_l3   = (M_ROWS / BM) * NGRP_L3;     // 64 * 38 = 2432
    const int sblocks = ((B_SZ * H_DIM) / 2 + 127) / 128; // 300

    gemm_tc<<<nblocks_full, 256, GEMM_SMEM_BYTES>>>(1, b1, NGRP_FULL);
    scan_kernel<<<sblocks, 128>>>(0, sent_len, out);

    gemm_tc<<<nblocks_full, 256, GEMM_SMEM_BYTES>>>(2, b2, NGRP_FULL);
    scan_kernel<<<sblocks, 128>>>(1, sent_len, out);

    // Layer 3: O-gate columns (n >= 4800) are never read (scan mode 2 uses
    // only Z and F, and layer-3 hidden output is unused) -> skip them.
    gemm_tc<<<nblocks_l3, 256, GEMM_SMEM_BYTES>>>(3, b3, NGRP_L3);
    scan_kernel<<<sblocks, 128>>>(2, sent_len, out);
}

// round 14
// speedup vs baseline: 1.5002x; 1.1027x over previous
#include <cuda_runtime.h>
#include <cuda_fp16.h>
#include <math.h>
#include <stdint.h>

// ---------------------------------------------------------------------------
// Problem constants
// ---------------------------------------------------------------------------
#define S_LEN 256
#define B_SZ  32
#define E_DIM 300
#define H_DIM 2400
#define N3H   (3 * H_DIM)            // 7200
#define M_ROWS (S_LEN * B_SZ)        // 8192

#define K1PAD 320                    // 300 -> mult of 64
#define K2PAD 2432                   // 2400 -> mult of 64
#define NPAD  7296                   // 7200 -> mult of 128

#define BM 128
#define BN 128
#define BK 64
#define NSTAGE 3
#define NGRP_FULL 57                 // ceil(7200/128): layers 1,2
#define NGRP_L3   38                 // ceil(4800/128): layer 3 (O-gate unused)

// SMEM plane: 128 rows x 64 fp16 (128 B) padded to 144 B (conflict-free ldmatrix)
#define ROWB 144
#define PLANE_BYTES (128 * ROWB)     // 18432
#define OFF_A   0
#define OFF_B   PLANE_BYTES
#define STAGE_BYTES (2 * PLANE_BYTES)            // 36864
#define GEMM_SMEM_BYTES (NSTAGE * STAGE_BYTES)   // 110592 (x2 CTA = 221184 <= 228K)

// ---------------------------------------------------------------------------
// Scratch (__device__ globals: allocation-free; zero-initialized at load,
// so padded K/N regions read as 0)
// ---------------------------------------------------------------------------
__device__ __align__(16) __half g_A1[(size_t)M_ROWS * K1PAD];
__device__ __align__(16) __half g_Ax[(size_t)M_ROWS * K2PAD];
__device__ __align__(16) __half g_W1[(size_t)NPAD * K1PAD];
__device__ __align__(16) __half g_W2[(size_t)NPAD * K2PAD];
__device__ __align__(16) __half g_W3[(size_t)NPAD * K2PAD];
__device__ __align__(16) __half g_gates[(size_t)M_ROWS * N3H];   // fp16 gates
__device__ float g_acc[B_SZ * H_DIM];

// ---------------------------------------------------------------------------
__device__ __forceinline__ uint32_t smem_u32(const void* p) {
    uint32_t a;
    asm("{ .reg .u64 t; cvta.to.shared.u64 t, %1; cvt.u32.u64 %0, t; }" : "=r"(a) : "l"(p));
    return a;
}
__device__ __forceinline__ float sigmoid_f(float x) {
    return __fdividef(1.0f, 1.0f + __expf(-x));
}
__device__ __forceinline__ float tanh_fast(float x) {
    return 1.0f - __fdividef(2.0f, __expf(2.0f * x) + 1.0f);
}

#define CP_ASYNC16(dst, src) \
    asm volatile("cp.async.cg.shared.global [%0], [%1], 16;" :: "r"(dst), "l"(src) : "memory")
#define CP_COMMIT() asm volatile("cp.async.commit_group;" ::: "memory")
#define CP_WAIT(n)  asm volatile("cp.async.wait_group %0;" :: "n"(n) : "memory")

#define LDSM_X4(r0, r1, r2, r3, addr) \
    asm volatile("ldmatrix.sync.aligned.m8n8.x4.shared.b16 {%0,%1,%2,%3}, [%4];" \
                 : "=r"(r0), "=r"(r1), "=r"(r2), "=r"(r3) : "r"(addr))

#define MMA_FP16(d, a, b0, b1) \
    asm volatile("mma.sync.aligned.m16n8k16.row.col.f32.f16.f16.f32 " \
                 "{%0,%1,%2,%3}, {%4,%5,%6,%7}, {%8,%9}, {%0,%1,%2,%3};" \
                 : "+f"((d)[0]), "+f"((d)[1]), "+f"((d)[2]), "+f"((d)[3]) \
                 : "r"((a)[0]), "r"((a)[1]), "r"((a)[2]), "r"((a)[3]), "r"(b0), "r"(b1))

// ---------------------------------------------------------------------------
// fp32 -> fp16 conversions, vectorized. One launch covers all three W's.
// ---------------------------------------------------------------------------
__global__ void cvt_W_all(const float* __restrict__ w1in,
                          const float* __restrict__ w2in,
                          const float* __restrict__ w3in) {
    const int which = blockIdx.y;
    const float* in;
    __half* w;
    int K4, Kpad;
    if (which == 0)      { in = w1in; w = g_W1; K4 = E_DIM / 4; Kpad = K1PAD; }
    else if (which == 1) { in = w2in; w = g_W2; K4 = H_DIM / 4; Kpad = K2PAD; }
    else                 { in = w3in; w = g_W3; K4 = H_DIM / 4; Kpad = K2PAD; }
    const int r = blockIdx.x;
    const float4* row = (const float4*)(in + (size_t)r * (K4 * 4));
    for (int k4 = threadIdx.x; k4 < K4; k4 += blockDim.x) {
        const float4 x = row[k4];
        __half2 h01 = __floats2half2_rn(x.x, x.y);
        __half2 h23 = __floats2half2_rn(x.z, x.w);
        uint2 ph;
        ph.x = *(uint32_t*)&h01; ph.y = *(uint32_t*)&h23;
        *(uint2*)(w + (size_t)r * Kpad + k4 * 4) = ph;
    }
}

__global__ void cvt_A1_kernel(const float* __restrict__ sent) {
    const int r = blockIdx.x;
    const float4* row = (const float4*)(sent + (size_t)r * E_DIM);
    for (int k4 = threadIdx.x; k4 < E_DIM / 4; k4 += blockDim.x) {
        const float4 x = row[k4];
        __half2 h01 = __floats2half2_rn(x.x, x.y);
        __half2 h23 = __floats2half2_rn(x.z, x.w);
        uint2 ph;
        ph.x = *(uint32_t*)&h01; ph.y = *(uint32_t*)&h23;
        *(uint2*)(g_A1 + (size_t)r * K1PAD + k4 * 4) = ph;
    }
}

// ---------------------------------------------------------------------------
// fp16 HMMA GEMM (fp32 accum): g_gates[m,n] = act( A[m,:].W[n,:] + bias[n] )
// BM=128, BN=128, BK=64, warp tile 64x32, 3-stage pipeline, 2 CTAs/SM.
// ngrp parametrizes the n-extent (layer 3 skips the unused O-gate columns).
// ---------------------------------------------------------------------------
__global__ __launch_bounds__(256, 2) void gemm_tc(int layer, const float* __restrict__ bias,
                                                  int ngrp) {
    const __half *A, *W;
    int Kpad;
    if (layer == 1)      { A = g_A1; W = g_W1; Kpad = K1PAD; }
    else if (layer == 2) { A = g_Ax; W = g_W2; Kpad = K2PAD; }
    else                 { A = g_Ax; W = g_W3; Kpad = K2PAD; }
    const int NT = Kpad / BK;

    // m-strip swizzle for L2 reuse: strips of 8 m-groups, n fastest
    const int bx = blockIdx.x;
    const int strip = bx / (8 * ngrp);
    const int rem   = bx % (8 * ngrp);
    const int mg    = strip * 8 + (rem % 8);
    const int ng    = rem / 8;
    const int m0 = mg * BM;
    const int n0 = ng * BN;

    extern __shared__ char smem_raw[];
    const uint32_t sbase = smem_u32(smem_raw);

    const int tid = threadIdx.x;
    const int wid = tid >> 5;
    const int lid = tid & 31;
    const int wm = (wid & 1) * 64;
    const int wn = (wid >> 1) * 32;

    auto load_chunk = [&](int t, int slot) {
        const uint32_t st = sbase + (uint32_t)slot * STAGE_BYTES;
        const int kc = t * BK;
#pragma unroll
        for (int i = 0; i < 4; i++) {
            const int u = tid + i * 256;
            const int r = u >> 3, c = u & 7;
            const uint32_t so = (uint32_t)(r * ROWB + c * 16);
            CP_ASYNC16(st + OFF_A + so, A + (size_t)(m0 + r) * Kpad + kc + c * 8);
            CP_ASYNC16(st + OFF_B + so, W + (size_t)(n0 + r) * Kpad + kc + c * 8);
        }
        CP_COMMIT();
    };

    float d[4][4][4];
#pragma unroll
    for (int mi = 0; mi < 4; mi++)
#pragma unroll
        for (int ni = 0; ni < 4; ni++)
#pragma unroll
            for (int q = 0; q < 4; q++) d[mi][ni][q] = 0.0f;

    const uint32_t a_row = (uint32_t)(wm + (lid & 15));
    const uint32_t a_kb  = (uint32_t)((lid >> 4) * 16);
    const uint32_t b_row = (uint32_t)(wn + (lid & 7) + ((lid >> 4) & 1) * 8);
    const uint32_t b_kb  = (uint32_t)(((lid >> 3) & 1) * 16);

    // Prologue: fill 2 of 3 stages
    load_chunk(0, 0);
    load_chunk(1, 1);

    for (int t = 0; t < NT; ++t) {
        CP_WAIT(1);            // chunk t landed (t+1 may still be in flight)
        __syncthreads();       // all warps done with slot being refilled

        if (t + 2 < NT) load_chunk(t + 2, (t + 2) % NSTAGE);
        else CP_COMMIT();      // keep outstanding-group count uniform

        const uint32_t st = sbase + (uint32_t)(t % NSTAGE) * STAGE_BYTES;
#pragma unroll
        for (int ks = 0; ks < 4; ks++) {
            const uint32_t kbyte = (uint32_t)(ks * 32);
            uint32_t af[4][4];
#pragma unroll
            for (int mi = 0; mi < 4; mi++) {
                const uint32_t ra = st + OFF_A + (a_row + mi * 16) * ROWB + kbyte + a_kb;
                LDSM_X4(af[mi][0], af[mi][1], af[mi][2], af[mi][3], ra);
            }
            uint32_t bf[4][2];
#pragma unroll
            for (int j = 0; j < 2; j++) {
                const uint32_t rb = st + OFF_B + (b_row + j * 16) * ROWB + kbyte + b_kb;
                LDSM_X4(bf[2*j][0], bf[2*j][1], bf[2*j+1][0], bf[2*j+1][1], rb);
            }
#pragma unroll
            for (int mi = 0; mi < 4; mi++)
#pragma unroll
                for (int ni = 0; ni < 4; ni++)
                    MMA_FP16(d[mi][ni], af[mi], bf[ni][0], bf[ni][1]);
        }
    }

    __syncthreads();

    // Epilogue: bias + activation + fp16 store
    const int er = lid >> 2;
    const int ec = (lid & 3) * 2;
#pragma unroll
    for (int mi = 0; mi < 4; mi++) {
#pragma unroll
        for (int ni = 0; ni < 4; ni++) {
            const int n = n0 + wn + ni * 8 + ec;     // even; H_DIM even -> no straddle
            if (n >= N3H) continue;
            const int m = m0 + wm + mi * 16 + er;
            const float2 bs = *(const float2*)(bias + n);
            const bool tA = (n < H_DIM);
            {
                const float y0 = d[mi][ni][0] + bs.x;
                const float y1 = d[mi][ni][1] + bs.y;
                const float v0 = tA ? tanh_fast(y0) : sigmoid_f(y0);
                const float v1 = tA ? tanh_fast(y1) : sigmoid_f(y1);
                *(__half2*)(g_gates + (size_t)m * N3H + n) = __floats2half2_rn(v0, v1);
            }
            {
                const float y0 = d[mi][ni][2] + bs.x;
                const float y1 = d[mi][ni][3] + bs.y;
                const float v0 = tA ? tanh_fast(y0) : sigmoid_f(y0);
                const float v1 = tA ? tanh_fast(y1) : sigmoid_f(y1);
                *(__half2*)(g_gates + (size_t)(m + 8) * N3H + n) = __floats2half2_rn(v0, v1);
            }
        }
    }
}

// ---------------------------------------------------------------------------
// fo-pool scan: 2 h-lanes/thread, depth-8 software-pipelined prefetch (R12
// optimum: regs 80, 53 us; SD=16 spilled at regs 130 and regressed to 134 us).
// ---------------------------------------------------------------------------
#define SD 8

__device__ __forceinline__ float2 ld_gates2(const __half* p) {
    const uint32_t u = *(const uint32_t*)p;
    return __half22float2(*(const __half2*)&u);
}

__global__ void scan_kernel(int mode, const int* __restrict__ sent_len,
                            float* __restrict__ out)
{
    const int tix = blockIdx.x * blockDim.x + threadIdx.x;
    if (tix >= (B_SZ * H_DIM) / 2) return;
    const int flat = tix * 2;
    const int b = flat / H_DIM;
    const int h = flat - b * H_DIM;       // even; H_DIM even -> no b straddle

    const size_t stride = (size_t)B_SZ * N3H;
    const __half* gp = g_gates + (size_t)b * N3H + h;

    float2 zb[SD], fb[SD], ob[SD];
    float2 c = make_float2(0.f, 0.f);

    if (mode != 2) {
        // Preload depth-SD window
#pragma unroll
        for (int i = 0; i < SD; i++) {
            const __half* q = gp + (size_t)i * stride;
            zb[i] = ld_gates2(q);
            fb[i] = ld_gates2(q + H_DIM);
            ob[i] = ld_gates2(q + 2 * H_DIM);
        }
        size_t xbase = (size_t)b * K2PAD + h;
        const size_t xstride = (size_t)B_SZ * K2PAD;
#pragma unroll 8
        for (int s = 0; s < S_LEN; ++s) {
            const int j = s & (SD - 1);
            const float2 z = zb[j], f = fb[j], o = ob[j];
            if (s + SD < S_LEN) {
                const __half* q = gp + (size_t)(s + SD) * stride;
                zb[j] = ld_gates2(q);
                fb[j] = ld_gates2(q + H_DIM);
                ob[j] = ld_gates2(q + 2 * H_DIM);
            }
            c.x = fmaf(f.x, c.x - z.x, z.x);
            c.y = fmaf(f.y, c.y - z.y, z.y);
            const __half2 hh = __floats2half2_rn(o.x * c.x, o.y * c.y);
            *(uint32_t*)(g_Ax + xbase) = *(const uint32_t*)&hh;
            xbase += xstride;
        }
    } else {
#pragma unroll
        for (int i = 0; i < SD; i++) {
            const __half* q = gp + (size_t)i * stride;
            zb[i] = ld_gates2(q);
            fb[i] = ld_gates2(q + H_DIM);
        }
#pragma unroll 8
        for (int s = 0; s < S_LEN; ++s) {
            const int j = s & (SD - 1);
            const float2 z = zb[j], f = fb[j];
            if (s + SD < S_LEN) {
                const __half* q = gp + (size_t)(s + SD) * stride;
                zb[j] = ld_gates2(q);
                fb[j] = ld_gates2(q + H_DIM);
            }
            c.x = fmaf(f.x, c.x - z.x, z.x);
            c.y = fmaf(f.y, c.y - z.y, z.y);
        }
    }

    if (mode == 0) {
        *(float2*)(g_acc + flat) = c;
    } else if (mode == 1) {
        float2 a = *(const float2*)(g_acc + flat);
        a.x += c.x; a.y += c.y;
        *(float2*)(g_acc + flat) = a;
    } else {
        const float inv = 1.0f / (float)sent_len[b];
        float2 a = *(const float2*)(g_acc + flat);
        float2 v;
        v.x = (a.x + c.x) * inv;
        v.y = (a.y + c.y) * inv;
        *(float2*)(out + flat) = v;
    }
}

// ---------------------------------------------------------------------------
extern "C" void kernel_launch(void* const* d_in, const int* in_sizes, int n_in,
                              void* d_out, int out_size)
{
    const float* sent     = (const float*)d_in[0];
    const int*   sent_len = (const int*)  d_in[1];
    const float* W1 = (const float*)d_in[2];
    const float* b1 = (const float*)d_in[3];
    const float* W2 = (const float*)d_in[4];
    const float* b2 = (const float*)d_in[5];
    const float* W3 = (const float*)d_in[6];
    const float* b3 = (const float*)d_in[7];
    float* out = (float*)d_out;

    cudaFuncSetAttribute(gemm_tc, cudaFuncAttributeMaxDynamicSharedMemorySize, GEMM_SMEM_BYTES);

    cvt_W_all<<<dim3(N3H, 3), 128>>>(W1, W2, W3);
    cvt_A1_kernel<<<M_ROWS, 64>>>(sent);

    const int nblocks_full = (M_ROWS / BM) * NGRP_FULL;   // 64 * 57 = 3648
    const int nblocks_l3   = (M_ROWS / BM) * NGRP_L3;     // 64 * 38 = 2432
    const int sblocks = ((B_SZ * H_DIM) / 2 + 127) / 128; // 300

    gemm_tc<<<nblocks_full, 256, GEMM_SMEM_BYTES>>>(1, b1, NGRP_FULL);
    scan_kernel<<<sblocks, 128>>>(0, sent_len, out);

    gemm_tc<<<nblocks_full, 256, GEMM_SMEM_BYTES>>>(2, b2, NGRP_FULL);
    scan_kernel<<<sblocks, 128>>>(1, sent_len, out);

    // Layer 3: O-gate columns (n >= 4800) are never read (scan mode 2 uses
    // only Z and F, and layer-3 hidden output is unused) -> skip them.
    gemm_tc<<<nblocks_l3, 256, GEMM_SMEM_BYTES>>>(3, b3, NGRP_L3);
    scan_kernel<<<sblocks, 128>>>(2, sent_len, out);
}

// round 15
// speedup vs baseline: 1.5552x; 1.0367x over previous
#include <cuda_runtime.h>
#include <cuda_fp16.h>
#include <math.h>
#include <stdint.h>

// ---------------------------------------------------------------------------
// Problem constants
// ---------------------------------------------------------------------------
#define S_LEN 256
#define B_SZ  32
#define E_DIM 300
#define H_DIM 2400
#define N3H   (3 * H_DIM)            // 7200
#define M_ROWS (S_LEN * B_SZ)        // 8192

#define K1PAD 320                    // 300 -> mult of 64
#define K2PAD 2432                   // 2400 -> mult of 64
#define NPAD  7296                   // 7200 -> mult of 128

#define BM 128
#define BN 128
#define BK 64
#define NSTAGE 3
#define NGRP_FULL 57                 // ceil(7200/128): layers 1,2
#define NGRP_L3   38                 // ceil(4800/128): layer 3 (O-gate unused)

// SMEM plane: 128 rows x 64 fp16 (128 B) padded to 144 B (conflict-free ldmatrix)
#define ROWB 144
#define PLANE_BYTES (128 * ROWB)     // 18432
#define OFF_A   0
#define OFF_B   PLANE_BYTES
#define STAGE_BYTES (2 * PLANE_BYTES)            // 36864
#define GEMM_SMEM_BYTES (NSTAGE * STAGE_BYTES)   // 110592 (x2 CTA = 221184 <= 228K)

// ---------------------------------------------------------------------------
// Scratch (__device__ globals: allocation-free; zero-initialized at load,
// so padded K/N regions read as 0)
// ---------------------------------------------------------------------------
__device__ __align__(16) __half g_A1[(size_t)M_ROWS * K1PAD];
__device__ __align__(16) __half g_Ax[(size_t)M_ROWS * K2PAD];
__device__ __align__(16) __half g_W1[(size_t)NPAD * K1PAD];
__device__ __align__(16) __half g_W2[(size_t)NPAD * K2PAD];
__device__ __align__(16) __half g_W3[(size_t)NPAD * K2PAD];
__device__ __align__(16) __half g_gates[(size_t)M_ROWS * N3H];   // fp16 gates
__device__ float g_acc[B_SZ * H_DIM];

// ---------------------------------------------------------------------------
__device__ __forceinline__ uint32_t smem_u32(const void* p) {
    uint32_t a;
    asm("{ .reg .u64 t; cvta.to.shared.u64 t, %1; cvt.u32.u64 %0, t; }" : "=r"(a) : "l"(p));
    return a;
}
__device__ __forceinline__ float sigmoid_f(float x) {
    return __fdividef(1.0f, 1.0f + __expf(-x));
}
__device__ __forceinline__ float tanh_fast(float x) {
    return 1.0f - __fdividef(2.0f, __expf(2.0f * x) + 1.0f);
}

#define CP_ASYNC16(dst, src) \
    asm volatile("cp.async.cg.shared.global [%0], [%1], 16;" :: "r"(dst), "l"(src) : "memory")
#define CP_COMMIT() asm volatile("cp.async.commit_group;" ::: "memory")
#define CP_WAIT(n)  asm volatile("cp.async.wait_group %0;" :: "n"(n) : "memory")

#define LDSM_X4(r0, r1, r2, r3, addr) \
    asm volatile("ldmatrix.sync.aligned.m8n8.x4.shared.b16 {%0,%1,%2,%3}, [%4];" \
                 : "=r"(r0), "=r"(r1), "=r"(r2), "=r"(r3) : "r"(addr))

#define MMA_FP16(d, a, b0, b1) \
    asm volatile("mma.sync.aligned.m16n8k16.row.col.f32.f16.f16.f32 " \
                 "{%0,%1,%2,%3}, {%4,%5,%6,%7}, {%8,%9}, {%0,%1,%2,%3};" \
                 : "+f"((d)[0]), "+f"((d)[1]), "+f"((d)[2]), "+f"((d)[3]) \
                 : "r"((a)[0]), "r"((a)[1]), "r"((a)[2]), "r"((a)[3]), "r"(b0), "r"(b1))

// ---------------------------------------------------------------------------
// fp32 -> fp16 conversions, vectorized. One launch covers all three W's.
// ---------------------------------------------------------------------------
__global__ void cvt_W_all(const float* __restrict__ w1in,
                          const float* __restrict__ w2in,
                          const float* __restrict__ w3in) {
    const int which = blockIdx.y;
    const float* in;
    __half* w;
    int K4, Kpad;
    if (which == 0)      { in = w1in; w = g_W1; K4 = E_DIM / 4; Kpad = K1PAD; }
    else if (which == 1) { in = w2in; w = g_W2; K4 = H_DIM / 4; Kpad = K2PAD; }
    else                 { in = w3in; w = g_W3; K4 = H_DIM / 4; Kpad = K2PAD; }
    const int r = blockIdx.x;
    const float4* row = (const float4*)(in + (size_t)r * (K4 * 4));
    for (int k4 = threadIdx.x; k4 < K4; k4 += blockDim.x) {
        const float4 x = row[k4];
        __half2 h01 = __floats2half2_rn(x.x, x.y);
        __half2 h23 = __floats2half2_rn(x.z, x.w);
        uint2 ph;
        ph.x = *(uint32_t*)&h01; ph.y = *(uint32_t*)&h23;
        *(uint2*)(w + (size_t)r * Kpad + k4 * 4) = ph;
    }
}

__global__ void cvt_A1_kernel(const float* __restrict__ sent) {
    const int r = blockIdx.x;
    const float4* row = (const float4*)(sent + (size_t)r * E_DIM);
    for (int k4 = threadIdx.x; k4 < E_DIM / 4; k4 += blockDim.x) {
        const float4 x = row[k4];
        __half2 h01 = __floats2half2_rn(x.x, x.y);
        __half2 h23 = __floats2half2_rn(x.z, x.w);
        uint2 ph;
        ph.x = *(uint32_t*)&h01; ph.y = *(uint32_t*)&h23;
        *(uint2*)(g_A1 + (size_t)r * K1PAD + k4 * 4) = ph;
    }
}

// ---------------------------------------------------------------------------
// fp16 HMMA GEMM (fp32 accum): g_gates[m,n] = act( A[m,:].W[n,:] + bias[n] )
// BM=128, BN=128, BK=64, warp tile 64x32, 3-stage pipeline, 2 CTAs/SM.
// ngrp parametrizes the n-extent (layer 3 skips the unused O-gate columns).
// ---------------------------------------------------------------------------
__global__ __launch_bounds__(256, 2) void gemm_tc(int layer, const float* __restrict__ bias,
                                                  int ngrp) {
    const __half *A, *W;
    int Kpad;
    if (layer == 1)      { A = g_A1; W = g_W1; Kpad = K1PAD; }
    else if (layer == 2) { A = g_Ax; W = g_W2; Kpad = K2PAD; }
    else                 { A = g_Ax; W = g_W3; Kpad = K2PAD; }
    const int NT = Kpad / BK;

    // m-strip swizzle for L2 reuse: strips of 8 m-groups, n fastest
    const int bx = blockIdx.x;
    const int strip = bx / (8 * ngrp);
    const int rem   = bx % (8 * ngrp);
    const int mg    = strip * 8 + (rem % 8);
    const int ng    = rem / 8;
    const int m0 = mg * BM;
    const int n0 = ng * BN;

    extern __shared__ char smem_raw[];
    const uint32_t sbase = smem_u32(smem_raw);

    const int tid = threadIdx.x;
    const int wid = tid >> 5;
    const int lid = tid & 31;
    const int wm = (wid & 1) * 64;
    const int wn = (wid >> 1) * 32;

    auto load_chunk = [&](int t, int slot) {
        const uint32_t st = sbase + (uint32_t)slot * STAGE_BYTES;
        const int kc = t * BK;
#pragma unroll
        for (int i = 0; i < 4; i++) {
            const int u = tid + i * 256;
            const int r = u >> 3, c = u & 7;
            const uint32_t so = (uint32_t)(r * ROWB + c * 16);
            CP_ASYNC16(st + OFF_A + so, A + (size_t)(m0 + r) * Kpad + kc + c * 8);
            CP_ASYNC16(st + OFF_B + so, W + (size_t)(n0 + r) * Kpad + kc + c * 8);
        }
        CP_COMMIT();
    };

    float d[4][4][4];
#pragma unroll
    for (int mi = 0; mi < 4; mi++)
#pragma unroll
        for (int ni = 0; ni < 4; ni++)
#pragma unroll
            for (int q = 0; q < 4; q++) d[mi][ni][q] = 0.0f;

    const uint32_t a_row = (uint32_t)(wm + (lid & 15));
    const uint32_t a_kb  = (uint32_t)((lid >> 4) * 16);
    const uint32_t b_row = (uint32_t)(wn + (lid & 7) + ((lid >> 4) & 1) * 8);
    const uint32_t b_kb  = (uint32_t)(((lid >> 3) & 1) * 16);

    // Prologue: fill 2 of 3 stages
    load_chunk(0, 0);
    load_chunk(1, 1);

    for (int t = 0; t < NT; ++t) {
        CP_WAIT(1);            // chunk t landed (t+1 may still be in flight)
        __syncthreads();       // all warps done with slot being refilled

        if (t + 2 < NT) load_chunk(t + 2, (t + 2) % NSTAGE);
        else CP_COMMIT();      // keep outstanding-group count uniform

        const uint32_t st = sbase + (uint32_t)(t % NSTAGE) * STAGE_BYTES;
#pragma unroll
        for (int ks = 0; ks < 4; ks++) {
            const uint32_t kbyte = (uint32_t)(ks * 32);
            uint32_t af[4][4];
#pragma unroll
            for (int mi = 0; mi < 4; mi++) {
                const uint32_t ra = st + OFF_A + (a_row + mi * 16) * ROWB + kbyte + a_kb;
                LDSM_X4(af[mi][0], af[mi][1], af[mi][2], af[mi][3], ra);
            }
            uint32_t bf[4][2];
#pragma unroll
            for (int j = 0; j < 2; j++) {
                const uint32_t rb = st + OFF_B + (b_row + j * 16) * ROWB + kbyte + b_kb;
                LDSM_X4(bf[2*j][0], bf[2*j][1], bf[2*j+1][0], bf[2*j+1][1], rb);
            }
#pragma unroll
            for (int mi = 0; mi < 4; mi++)
#pragma unroll
                for (int ni = 0; ni < 4; ni++)
                    MMA_FP16(d[mi][ni], af[mi], bf[ni][0], bf[ni][1]);
        }
    }

    __syncthreads();

    // Epilogue: bias + activation + fp16 store
    const int er = lid >> 2;
    const int ec = (lid & 3) * 2;
#pragma unroll
    for (int mi = 0; mi < 4; mi++) {
#pragma unroll
        for (int ni = 0; ni < 4; ni++) {
            const int n = n0 + wn + ni * 8 + ec;     // even; H_DIM even -> no straddle
            if (n >= N3H) continue;
            const int m = m0 + wm + mi * 16 + er;
            const float2 bs = *(const float2*)(bias + n);
            const bool tA = (n < H_DIM);
            {
                const float y0 = d[mi][ni][0] + bs.x;
                const float y1 = d[mi][ni][1] + bs.y;
                const float v0 = tA ? tanh_fast(y0) : sigmoid_f(y0);
                const float v1 = tA ? tanh_fast(y1) : sigmoid_f(y1);
                *(__half2*)(g_gates + (size_t)m * N3H + n) = __floats2half2_rn(v0, v1);
            }
            {
                const float y0 = d[mi][ni][2] + bs.x;
                const float y1 = d[mi][ni][3] + bs.y;
                const float v0 = tA ? tanh_fast(y0) : sigmoid_f(y0);
                const float v1 = tA ? tanh_fast(y1) : sigmoid_f(y1);
                *(__half2*)(g_gates + (size_t)(m + 8) * N3H + n) = __floats2half2_rn(v0, v1);
            }
        }
    }
}

// ---------------------------------------------------------------------------
// fo-pool scan: 2 h-lanes/thread, depth-16 prefetch with RAW uint32 FIFOs
// (converted at consume). 48 outstanding 4B loads/thread -> ~7.4 MB in flight
// chip-wide at ~80 regs (R13's float2 FIFOs cost 2x regs and spilled).
// ---------------------------------------------------------------------------
#define SD 16

__device__ __forceinline__ float2 cvt_h2(uint32_t u) {
    return __half22float2(*(const __half2*)&u);
}
__device__ __forceinline__ uint32_t ld_u32(const __half* p) {
    return *(const uint32_t*)p;
}

__global__ void scan_kernel(int mode, const int* __restrict__ sent_len,
                            float* __restrict__ out)
{
    const int tix = blockIdx.x * blockDim.x + threadIdx.x;
    if (tix >= (B_SZ * H_DIM) / 2) return;
    const int flat = tix * 2;
    const int b = flat / H_DIM;
    const int h = flat - b * H_DIM;       // even; H_DIM even -> no b straddle

    const size_t stride = (size_t)B_SZ * N3H;
    const __half* gp = g_gates + (size_t)b * N3H + h;

    float2 c = make_float2(0.f, 0.f);

    if (mode != 2) {
        uint32_t zr[SD], fr[SD], orr[SD];
#pragma unroll
        for (int i = 0; i < SD; i++) {
            const __half* q = gp + (size_t)i * stride;
            zr[i]  = ld_u32(q);
            fr[i]  = ld_u32(q + H_DIM);
            orr[i] = ld_u32(q + 2 * H_DIM);
        }
        size_t xbase = (size_t)b * K2PAD + h;
        const size_t xstride = (size_t)B_SZ * K2PAD;
#pragma unroll 16
        for (int s = 0; s < S_LEN; ++s) {
            const int j = s & (SD - 1);
            const float2 z = cvt_h2(zr[j]);
            const float2 f = cvt_h2(fr[j]);
            const float2 o = cvt_h2(orr[j]);
            if (s + SD < S_LEN) {
                const __half* q = gp + (size_t)(s + SD) * stride;
                zr[j]  = ld_u32(q);
                fr[j]  = ld_u32(q + H_DIM);
                orr[j] = ld_u32(q + 2 * H_DIM);
            }
            c.x = fmaf(f.x, c.x - z.x, z.x);
            c.y = fmaf(f.y, c.y - z.y, z.y);
            const __half2 hh = __floats2half2_rn(o.x * c.x, o.y * c.y);
            *(uint32_t*)(g_Ax + xbase) = *(const uint32_t*)&hh;
            xbase += xstride;
        }
    } else {
        uint32_t zr[SD], fr[SD];
#pragma unroll
        for (int i = 0; i < SD; i++) {
            const __half* q = gp + (size_t)i * stride;
            zr[i] = ld_u32(q);
            fr[i] = ld_u32(q + H_DIM);
        }
#pragma unroll 16
        for (int s = 0; s < S_LEN; ++s) {
            const int j = s & (SD - 1);
            const float2 z = cvt_h2(zr[j]);
            const float2 f = cvt_h2(fr[j]);
            if (s + SD < S_LEN) {
                const __half* q = gp + (size_t)(s + SD) * stride;
                zr[j] = ld_u32(q);
                fr[j] = ld_u32(q + H_DIM);
            }
            c.x = fmaf(f.x, c.x - z.x, z.x);
            c.y = fmaf(f.y, c.y - z.y, z.y);
        }
    }

    if (mode == 0) {
        *(float2*)(g_acc + flat) = c;
    } else if (mode == 1) {
        float2 a = *(const float2*)(g_acc + flat);
        a.x += c.x; a.y += c.y;
        *(float2*)(g_acc + flat) = a;
    } else {
        const float inv = 1.0f / (float)sent_len[b];
        float2 a = *(const float2*)(g_acc + flat);
        float2 v;
        v.x = (a.x + c.x) * inv;
        v.y = (a.y + c.y) * inv;
        *(float2*)(out + flat) = v;
    }
}

// ---------------------------------------------------------------------------
extern "C" void kernel_launch(void* const* d_in, const int* in_sizes, int n_in,
                              void* d_out, int out_size)
{
    const float* sent     = (const float*)d_in[0];
    const int*   sent_len = (const int*)  d_in[1];
    const float* W1 = (const float*)d_in[2];
    const float* b1 = (const float*)d_in[3];
    const float* W2 = (const float*)d_in[4];
    const float* b2 = (const float*)d_in[5];
    const float* W3 = (const float*)d_in[6];
    const float* b3 = (const float*)d_in[7];
    float* out = (float*)d_out;

    cudaFuncSetAttribute(gemm_tc, cudaFuncAttributeMaxDynamicSharedMemorySize, GEMM_SMEM_BYTES);

    cvt_W_all<<<dim3(N3H, 3), 128>>>(W1, W2, W3);
    cvt_A1_kernel<<<M_ROWS, 64>>>(sent);

    const int nblocks_full = (M_ROWS / BM) * NGRP_FULL;   // 64 * 57 = 3648
    const int nblocks_l3   = (M_ROWS / BM) * NGRP_L3;     // 64 * 38 = 2432
    const int sblocks = ((B_SZ * H_DIM) / 2 + 127) / 128; // 300

    gemm_tc<<<nblocks_full, 256, GEMM_SMEM_BYTES>>>(1, b1, NGRP_FULL);
    scan_kernel<<<sblocks, 128>>>(0, sent_len, out);

    gemm_tc<<<nblocks_full, 256, GEMM_SMEM_BYTES>>>(2, b2, NGRP_FULL);
    scan_kernel<<<sblocks, 128>>>(1, sent_len, out);

    // Layer 3: O-gate columns (n >= 4800) are never read (scan mode 2 uses
    // only Z and F, and layer-3 hidden output is unused) -> skip them.
    gemm_tc<<<nblocks_l3, 256, GEMM_SMEM_BYTES>>>(3, b3, NGRP_L3);
    scan_kernel<<<sblocks, 128>>>(2, sent_len, out);
}

// round 16
// speedup vs baseline: 1.5639x; 1.0056x over previous
#include <cuda_runtime.h>
#include <cuda_fp16.h>
#include <math.h>
#include <stdint.h>

// ---------------------------------------------------------------------------
// Problem constants
// ---------------------------------------------------------------------------
#define S_LEN 256
#define B_SZ  32
#define E_DIM 300
#define H_DIM 2400
#define N3H   (3 * H_DIM)            // 7200
#define M_ROWS (S_LEN * B_SZ)        // 8192

#define K1PAD 320                    // 300 -> mult of 64
#define K2PAD 2432                   // 2400 -> mult of 64
#define NPAD  7296                   // 7200 -> mult of 128

#define BM 128
#define BN 128
#define BK 64
#define NSTAGE 3
#define NGRP_FULL 57                 // ceil(7200/128): layers 1,2
#define NGRP_L3   38                 // ceil(4800/128): layer 3 (O-gate unused)

// SMEM plane: 128 rows x 64 fp16 (128 B) padded to 144 B (conflict-free ldmatrix)
#define ROWB 144
#define PLANE_BYTES (128 * ROWB)     // 18432
#define OFF_A   0
#define OFF_B   PLANE_BYTES
#define STAGE_BYTES (2 * PLANE_BYTES)            // 36864
#define GEMM_SMEM_BYTES (NSTAGE * STAGE_BYTES)   // 110592 (x2 CTA = 221184 <= 228K)

// ---------------------------------------------------------------------------
// Scratch (__device__ globals: allocation-free; zero-initialized at load,
// so padded K/N regions read as 0)
// ---------------------------------------------------------------------------
__device__ __align__(16) __half g_A1[(size_t)M_ROWS * K1PAD];
__device__ __align__(16) __half g_Ax[(size_t)M_ROWS * K2PAD];
__device__ __align__(16) __half g_W1[(size_t)NPAD * K1PAD];
__device__ __align__(16) __half g_W2[(size_t)NPAD * K2PAD];
__device__ __align__(16) __half g_W3[(size_t)NPAD * K2PAD];
__device__ __align__(16) __half g_gates[(size_t)M_ROWS * N3H];   // fp16 gates
__device__ float g_acc[B_SZ * H_DIM];

// ---------------------------------------------------------------------------
__device__ __forceinline__ uint32_t smem_u32(const void* p) {
    uint32_t a;
    asm("{ .reg .u64 t; cvta.to.shared.u64 t, %1; cvt.u32.u64 %0, t; }" : "=r"(a) : "l"(p));
    return a;
}
__device__ __forceinline__ float sigmoid_f(float x) {
    return __fdividef(1.0f, 1.0f + __expf(-x));
}
__device__ __forceinline__ float tanh_fast(float x) {
    return 1.0f - __fdividef(2.0f, __expf(2.0f * x) + 1.0f);
}

#define CP_ASYNC16(dst, src) \
    asm volatile("cp.async.cg.shared.global [%0], [%1], 16;" :: "r"(dst), "l"(src) : "memory")
#define CP_COMMIT() asm volatile("cp.async.commit_group;" ::: "memory")
#define CP_WAIT(n)  asm volatile("cp.async.wait_group %0;" :: "n"(n) : "memory")

#define LDSM_X4(r0, r1, r2, r3, addr) \
    asm volatile("ldmatrix.sync.aligned.m8n8.x4.shared.b16 {%0,%1,%2,%3}, [%4];" \
                 : "=r"(r0), "=r"(r1), "=r"(r2), "=r"(r3) : "r"(addr))

#define MMA_FP16(d, a, b0, b1) \
    asm volatile("mma.sync.aligned.m16n8k16.row.col.f32.f16.f16.f32 " \
                 "{%0,%1,%2,%3}, {%4,%5,%6,%7}, {%8,%9}, {%0,%1,%2,%3};" \
                 : "+f"((d)[0]), "+f"((d)[1]), "+f"((d)[2]), "+f"((d)[3]) \
                 : "r"((a)[0]), "r"((a)[1]), "r"((a)[2]), "r"((a)[3]), "r"(b0), "r"(b1))

// ---------------------------------------------------------------------------
// Unified fp32 -> fp16 conversion: one flat launch covers W1, W2, W3, A1.
// Each thread handles one 4-element group; divisions are by constants.
// ---------------------------------------------------------------------------
#define G_W1 (N3H * (E_DIM / 4))                 // 540000
#define G_W2 (N3H * (H_DIM / 4))                 // 4320000
#define G_W3 (N3H * (H_DIM / 4))                 // 4320000
#define G_A1 (M_ROWS * (E_DIM / 4))              // 614400
#define G_TOTAL (G_W1 + G_W2 + G_W3 + G_A1)      // 9794400

__device__ __forceinline__ void cvt_group(const float* __restrict__ in, __half* __restrict__ outp,
                                          int r, int c4, int K, int Kpad) {
    const float4 x = *(const float4*)(in + (size_t)r * K + c4 * 4);
    __half2 h01 = __floats2half2_rn(x.x, x.y);
    __half2 h23 = __floats2half2_rn(x.z, x.w);
    uint2 ph;
    ph.x = *(uint32_t*)&h01; ph.y = *(uint32_t*)&h23;
    *(uint2*)(outp + (size_t)r * Kpad + c4 * 4) = ph;
}

__global__ void cvt_all(const float* __restrict__ sent,
                        const float* __restrict__ w1,
                        const float* __restrict__ w2,
                        const float* __restrict__ w3) {
    int g = blockIdx.x * blockDim.x + threadIdx.x;
    if (g >= G_TOTAL) return;
    if (g < G_W1) {
        cvt_group(w1, g_W1, g / (E_DIM / 4), g % (E_DIM / 4), E_DIM, K1PAD);
    } else if (g < G_W1 + G_W2) {
        g -= G_W1;
        cvt_group(w2, g_W2, g / (H_DIM / 4), g % (H_DIM / 4), H_DIM, K2PAD);
    } else if (g < G_W1 + G_W2 + G_W3) {
        g -= G_W1 + G_W2;
        cvt_group(w3, g_W3, g / (H_DIM / 4), g % (H_DIM / 4), H_DIM, K2PAD);
    } else {
        g -= G_W1 + G_W2 + G_W3;
        cvt_group(sent, g_A1, g / (E_DIM / 4), g % (E_DIM / 4), E_DIM, K1PAD);
    }
}

// ---------------------------------------------------------------------------
// fp16 HMMA GEMM (fp32 accum): g_gates[m,n] = act( A[m,:].W[n,:] + bias[n] )
// BM=128, BN=128, BK=64, warp tile 64x32, 3-stage pipeline, 2 CTAs/SM.
// ngrp parametrizes the n-extent (layer 3 skips the unused O-gate columns).
// ---------------------------------------------------------------------------
__global__ __launch_bounds__(256, 2) void gemm_tc(int layer, const float* __restrict__ bias,
                                                  int ngrp) {
    const __half *A, *W;
    int Kpad;
    if (layer == 1)      { A = g_A1; W = g_W1; Kpad = K1PAD; }
    else if (layer == 2) { A = g_Ax; W = g_W2; Kpad = K2PAD; }
    else                 { A = g_Ax; W = g_W3; Kpad = K2PAD; }
    const int NT = Kpad / BK;

    // m-strip swizzle for L2 reuse: strips of 8 m-groups, n fastest
    const int bx = blockIdx.x;
    const int strip = bx / (8 * ngrp);
    const int rem   = bx % (8 * ngrp);
    const int mg    = strip * 8 + (rem % 8);
    const int ng    = rem / 8;
    const int m0 = mg * BM;
    const int n0 = ng * BN;

    extern __shared__ char smem_raw[];
    const uint32_t sbase = smem_u32(smem_raw);

    const int tid = threadIdx.x;
    const int wid = tid >> 5;
    const int lid = tid & 31;
    const int wm = (wid & 1) * 64;
    const int wn = (wid >> 1) * 32;

    auto load_chunk = [&](int t, int slot) {
        const uint32_t st = sbase + (uint32_t)slot * STAGE_BYTES;
        const int kc = t * BK;
#pragma unroll
        for (int i = 0; i < 4; i++) {
            const int u = tid + i * 256;
            const int r = u >> 3, c = u & 7;
            const uint32_t so = (uint32_t)(r * ROWB + c * 16);
            CP_ASYNC16(st + OFF_A + so, A + (size_t)(m0 + r) * Kpad + kc + c * 8);
            CP_ASYNC16(st + OFF_B + so, W + (size_t)(n0 + r) * Kpad + kc + c * 8);
        }
        CP_COMMIT();
    };

    float d[4][4][4];
#pragma unroll
    for (int mi = 0; mi < 4; mi++)
#pragma unroll
        for (int ni = 0; ni < 4; ni++)
#pragma unroll
            for (int q = 0; q < 4; q++) d[mi][ni][q] = 0.0f;

    const uint32_t a_row = (uint32_t)(wm + (lid & 15));
    const uint32_t a_kb  = (uint32_t)((lid >> 4) * 16);
    const uint32_t b_row = (uint32_t)(wn + (lid & 7) + ((lid >> 4) & 1) * 8);
    const uint32_t b_kb  = (uint32_t)(((lid >> 3) & 1) * 16);

    // Prologue: fill 2 of 3 stages
    load_chunk(0, 0);
    load_chunk(1, 1);

    for (int t = 0; t < NT; ++t) {
        CP_WAIT(1);            // chunk t landed (t+1 may still be in flight)
        __syncthreads();       // all warps done with slot being refilled

        if (t + 2 < NT) load_chunk(t + 2, (t + 2) % NSTAGE);
        else CP_COMMIT();      // keep outstanding-group count uniform

        const uint32_t st = sbase + (uint32_t)(t % NSTAGE) * STAGE_BYTES;
#pragma unroll
        for (int ks = 0; ks < 4; ks++) {
            const uint32_t kbyte = (uint32_t)(ks * 32);
            uint32_t af[4][4];
#pragma unroll
            for (int mi = 0; mi < 4; mi++) {
                const uint32_t ra = st + OFF_A + (a_row + mi * 16) * ROWB + kbyte + a_kb;
                LDSM_X4(af[mi][0], af[mi][1], af[mi][2], af[mi][3], ra);
            }
            uint32_t bf[4][2];
#pragma unroll
            for (int j = 0; j < 2; j++) {
                const uint32_t rb = st + OFF_B + (b_row + j * 16) * ROWB + kbyte + b_kb;
                LDSM_X4(bf[2*j][0], bf[2*j][1], bf[2*j+1][0], bf[2*j+1][1], rb);
            }
#pragma unroll
            for (int mi = 0; mi < 4; mi++)
#pragma unroll
                for (int ni = 0; ni < 4; ni++)
                    MMA_FP16(d[mi][ni], af[mi], bf[ni][0], bf[ni][1]);
        }
    }

    __syncthreads();

    // Epilogue: bias + activation + fp16 store
    const int er = lid >> 2;
    const int ec = (lid & 3) * 2;
#pragma unroll
    for (int mi = 0; mi < 4; mi++) {
#pragma unroll
        for (int ni = 0; ni < 4; ni++) {
            const int n = n0 + wn + ni * 8 + ec;     // even; H_DIM even -> no straddle
            if (n >= N3H) continue;
            const int m = m0 + wm + mi * 16 + er;
            const float2 bs = *(const float2*)(bias + n);
            const bool tA = (n < H_DIM);
            {
                const float y0 = d[mi][ni][0] + bs.x;
                const float y1 = d[mi][ni][1] + bs.y;
                const float v0 = tA ? tanh_fast(y0) : sigmoid_f(y0);
                const float v1 = tA ? tanh_fast(y1) : sigmoid_f(y1);
                *(__half2*)(g_gates + (size_t)m * N3H + n) = __floats2half2_rn(v0, v1);
            }
            {
                const float y0 = d[mi][ni][2] + bs.x;
                const float y1 = d[mi][ni][3] + bs.y;
                const float v0 = tA ? tanh_fast(y0) : sigmoid_f(y0);
                const float v1 = tA ? tanh_fast(y1) : sigmoid_f(y1);
                *(__half2*)(g_gates + (size_t)(m + 8) * N3H + n) = __floats2half2_rn(v0, v1);
            }
        }
    }
}

// ---------------------------------------------------------------------------
// fo-pool scan: 2 h-lanes/thread, raw-uint32 prefetch FIFOs.
// Modes 0/1 (Z,F,O): depth 16 (proven 72 regs / 4.07 TB/s).
// Mode 2 (Z,F only): depth 32 (2 arrays -> same reg budget, 2x in-flight).
// ---------------------------------------------------------------------------
__device__ __forceinline__ float2 cvt_h2(uint32_t u) {
    return __half22float2(*(const __half2*)&u);
}
__device__ __forceinline__ uint32_t ld_u32(const __half* p) {
    return *(const uint32_t*)p;
}

template <int MODE>
__global__ void scan_kernel(const int* __restrict__ sent_len,
                            float* __restrict__ out)
{
    const int tix = blockIdx.x * blockDim.x + threadIdx.x;
    if (tix >= (B_SZ * H_DIM) / 2) return;
    const int flat = tix * 2;
    const int b = flat / H_DIM;
    const int h = flat - b * H_DIM;       // even; H_DIM even -> no b straddle

    const size_t stride = (size_t)B_SZ * N3H;
    const __half* gp = g_gates + (size_t)b * N3H + h;

    float2 c = make_float2(0.f, 0.f);

    if (MODE != 2) {
        const int SD = 16;
        uint32_t zr[SD], fr[SD], orr[SD];
#pragma unroll
        for (int i = 0; i < SD; i++) {
            const __half* q = gp + (size_t)i * stride;
            zr[i]  = ld_u32(q);
            fr[i]  = ld_u32(q + H_DIM);
            orr[i] = ld_u32(q + 2 * H_DIM);
        }
        size_t xbase = (size_t)b * K2PAD + h;
        const size_t xstride = (size_t)B_SZ * K2PAD;
#pragma unroll 16
        for (int s = 0; s < S_LEN; ++s) {
            const int j = s & (SD - 1);
            const float2 z = cvt_h2(zr[j]);
            const float2 f = cvt_h2(fr[j]);
            const float2 o = cvt_h2(orr[j]);
            if (s + SD < S_LEN) {
                const __half* q = gp + (size_t)(s + SD) * stride;
                zr[j]  = ld_u32(q);
                fr[j]  = ld_u32(q + H_DIM);
                orr[j] = ld_u32(q + 2 * H_DIM);
            }
            c.x = fmaf(f.x, c.x - z.x, z.x);
            c.y = fmaf(f.y, c.y - z.y, z.y);
            const __half2 hh = __floats2half2_rn(o.x * c.x, o.y * c.y);
            *(uint32_t*)(g_Ax + xbase) = *(const uint32_t*)&hh;
            xbase += xstride;
        }
    } else {
        const int SD = 32;
        uint32_t zr[SD], fr[SD];
#pragma unroll
        for (int i = 0; i < SD; i++) {
            const __half* q = gp + (size_t)i * stride;
            zr[i] = ld_u32(q);
            fr[i] = ld_u32(q + H_DIM);
        }
#pragma unroll 32
        for (int s = 0; s < S_LEN; ++s) {
            const int j = s & (SD - 1);
            const float2 z = cvt_h2(zr[j]);
            const float2 f = cvt_h2(fr[j]);
            if (s + SD < S_LEN) {
                const __half* q = gp + (size_t)(s + SD) * stride;
                zr[j] = ld_u32(q);
                fr[j] = ld_u32(q + H_DIM);
            }
            c.x = fmaf(f.x, c.x - z.x, z.x);
            c.y = fmaf(f.y, c.y - z.y, z.y);
        }
    }

    if (MODE == 0) {
        *(float2*)(g_acc + flat) = c;
    } else if (MODE == 1) {
        float2 a = *(const float2*)(g_acc + flat);
        a.x += c.x; a.y += c.y;
        *(float2*)(g_acc + flat) = a;
    } else {
        const float inv = 1.0f / (float)sent_len[b];
        float2 a = *(const float2*)(g_acc + flat);
        float2 v;
        v.x = (a.x + c.x) * inv;
        v.y = (a.y + c.y) * inv;
        *(float2*)(out + flat) = v;
    }
}

// ---------------------------------------------------------------------------
extern "C" void kernel_launch(void* const* d_in, const int* in_sizes, int n_in,
                              void* d_out, int out_size)
{
    const float* sent     = (const float*)d_in[0];
    const int*   sent_len = (const int*)  d_in[1];
    const float* W1 = (const float*)d_in[2];
    const float* b1 = (const float*)d_in[3];
    const float* W2 = (const float*)d_in[4];
    const float* b2 = (const float*)d_in[5];
    const float* W3 = (const float*)d_in[6];
    const float* b3 = (const float*)d_in[7];
    float* out = (float*)d_out;

    cudaFuncSetAttribute(gemm_tc, cudaFuncAttributeMaxDynamicSharedMemorySize, GEMM_SMEM_BYTES);

    cvt_all<<<(G_TOTAL + 255) / 256, 256>>>(sent, W1, W2, W3);

    const int nblocks_full = (M_ROWS / BM) * NGRP_FULL;   // 64 * 57 = 3648
    const int nblocks_l3   = (M_ROWS / BM) * NGRP_L3;     // 64 * 38 = 2432
    const int sblocks = ((B_SZ * H_DIM) / 2 + 127) / 128; // 300

    gemm_tc<<<nblocks_full, 256, GEMM_SMEM_BYTES>>>(1, b1, NGRP_FULL);
    scan_kernel<0><<<sblocks, 128>>>(sent_len, out);

    gemm_tc<<<nblocks_full, 256, GEMM_SMEM_BYTES>>>(2, b2, NGRP_FULL);
    scan_kernel<1><<<sblocks, 128>>>(sent_len, out);

    // Layer 3: O-gate columns (n >= 4800) are never read (scan mode 2 uses
    // only Z and F, and layer-3 hidden output is unused) -> skip them.
    gemm_tc<<<nblocks_l3, 256, GEMM_SMEM_BYTES>>>(3, b3, NGRP_L3);
    scan_kernel<2><<<sblocks, 128>>>(sent_len, out);
}

// round 17
// speedup vs baseline: 1.5914x; 1.0176x over previous
#include <cuda_runtime.h>
#include <cuda_fp16.h>
#include <math.h>
#include <stdint.h>

// ---------------------------------------------------------------------------
// Problem constants
// ---------------------------------------------------------------------------
#define S_LEN 256
#define B_SZ  32
#define E_DIM 300
#define H_DIM 2400
#define N3H   (3 * H_DIM)            // 7200
#define M_ROWS (S_LEN * B_SZ)        // 8192

#define K1PAD 320                    // 300 -> mult of 64
#define K2PAD 2432                   // 2400 -> mult of 64
#define NPAD  7296                   // 7200 -> mult of 128

#define BM 128
#define BN 128
#define BK 64
#define NSTAGE 3
#define NGRP_FULL 57                 // ceil(7200/128): layers 1,2
#define NGRP_L3   38                 // ceil(4800/128): layer 3 (O-gate unused)

// SMEM plane: 128 rows x 64 fp16 (128 B) padded to 144 B (conflict-free ldmatrix)
#define ROWB 144
#define PLANE_BYTES (128 * ROWB)     // 18432
#define OFF_A   0
#define OFF_B   PLANE_BYTES
#define STAGE_BYTES (2 * PLANE_BYTES)            // 36864
#define GEMM_SMEM_BYTES (NSTAGE * STAGE_BYTES)   // 110592 (x2 CTA = 221184 <= 228K)

// ---------------------------------------------------------------------------
// Scratch (__device__ globals: allocation-free; zero-initialized at load,
// so padded K/N regions read as 0)
// ---------------------------------------------------------------------------
__device__ __align__(16) __half g_A1[(size_t)M_ROWS * K1PAD];
__device__ __align__(16) __half g_Ax[(size_t)M_ROWS * K2PAD];
__device__ __align__(16) __half g_W1[(size_t)NPAD * K1PAD];
__device__ __align__(16) __half g_W2[(size_t)NPAD * K2PAD];
__device__ __align__(16) __half g_W3[(size_t)NPAD * K2PAD];
__device__ __align__(16) __half g_gates[(size_t)M_ROWS * N3H];   // fp16 gates
__device__ float g_acc[B_SZ * H_DIM];

// ---------------------------------------------------------------------------
__device__ __forceinline__ uint32_t smem_u32(const void* p) {
    uint32_t a;
    asm("{ .reg .u64 t; cvta.to.shared.u64 t, %1; cvt.u32.u64 %0, t; }" : "=r"(a) : "l"(p));
    return a;
}
__device__ __forceinline__ float sigmoid_f(float x) {
    return __fdividef(1.0f, 1.0f + __expf(-x));
}
__device__ __forceinline__ float tanh_fast(float x) {
    return 1.0f - __fdividef(2.0f, __expf(2.0f * x) + 1.0f);
}

#define CP_ASYNC16(dst, src) \
    asm volatile("cp.async.cg.shared.global [%0], [%1], 16;" :: "r"(dst), "l"(src) : "memory")
#define CP_COMMIT() asm volatile("cp.async.commit_group;" ::: "memory")
#define CP_WAIT(n)  asm volatile("cp.async.wait_group %0;" :: "n"(n) : "memory")

#define LDSM_X4(r0, r1, r2, r3, addr) \
    asm volatile("ldmatrix.sync.aligned.m8n8.x4.shared.b16 {%0,%1,%2,%3}, [%4];" \
                 : "=r"(r0), "=r"(r1), "=r"(r2), "=r"(r3) : "r"(addr))

#define MMA_FP16(d, a, b0, b1) \
    asm volatile("mma.sync.aligned.m16n8k16.row.col.f32.f16.f16.f32 " \
                 "{%0,%1,%2,%3}, {%4,%5,%6,%7}, {%8,%9}, {%0,%1,%2,%3};" \
                 : "+f"((d)[0]), "+f"((d)[1]), "+f"((d)[2]), "+f"((d)[3]) \
                 : "r"((a)[0]), "r"((a)[1]), "r"((a)[2]), "r"((a)[3]), "r"(b0), "r"(b1))

// ---------------------------------------------------------------------------
// Unified fp32 -> fp16 conversion: one flat launch covers W1, W2, W3, A1.
// ---------------------------------------------------------------------------
#define G_W1 (N3H * (E_DIM / 4))                 // 540000
#define G_W2 (N3H * (H_DIM / 4))                 // 4320000
#define G_W3 (N3H * (H_DIM / 4))                 // 4320000
#define G_A1 (M_ROWS * (E_DIM / 4))              // 614400
#define G_TOTAL (G_W1 + G_W2 + G_W3 + G_A1)      // 9794400

__device__ __forceinline__ void cvt_group(const float* __restrict__ in, __half* __restrict__ outp,
                                          int r, int c4, int K, int Kpad) {
    const float4 x = *(const float4*)(in + (size_t)r * K + c4 * 4);
    __half2 h01 = __floats2half2_rn(x.x, x.y);
    __half2 h23 = __floats2half2_rn(x.z, x.w);
    uint2 ph;
    ph.x = *(uint32_t*)&h01; ph.y = *(uint32_t*)&h23;
    *(uint2*)(outp + (size_t)r * Kpad + c4 * 4) = ph;
}

__global__ void cvt_all(const float* __restrict__ sent,
                        const float* __restrict__ w1,
                        const float* __restrict__ w2,
                        const float* __restrict__ w3) {
    int g = blockIdx.x * blockDim.x + threadIdx.x;
    if (g >= G_TOTAL) return;
    if (g < G_W1) {
        cvt_group(w1, g_W1, g / (E_DIM / 4), g % (E_DIM / 4), E_DIM, K1PAD);
    } else if (g < G_W1 + G_W2) {
        g -= G_W1;
        cvt_group(w2, g_W2, g / (H_DIM / 4), g % (H_DIM / 4), H_DIM, K2PAD);
    } else if (g < G_W1 + G_W2 + G_W3) {
        g -= G_W1 + G_W2;
        cvt_group(w3, g_W3, g / (H_DIM / 4), g % (H_DIM / 4), H_DIM, K2PAD);
    } else {
        g -= G_W1 + G_W2 + G_W3;
        cvt_group(sent, g_A1, g / (E_DIM / 4), g % (E_DIM / 4), E_DIM, K1PAD);
    }
}

// ---------------------------------------------------------------------------
// fp16 HMMA GEMM (fp32 accum): g_gates[m,n] = act( A[m,:].W[n,:] + bias[n] )
// BM=128, BN=128, BK=64, warp tile 64x32, 3-stage cp.async pipeline,
// 2 CTAs/SM. Intra-chunk ks-pipelining: fragments for ks+1 load into the
// alternate register buffer while the MMAs of ks execute.
// ---------------------------------------------------------------------------
__global__ __launch_bounds__(256, 2) void gemm_tc(int layer, const float* __restrict__ bias,
                                                  int ngrp) {
    const __half *A, *W;
    int Kpad;
    if (layer == 1)      { A = g_A1; W = g_W1; Kpad = K1PAD; }
    else if (layer == 2) { A = g_Ax; W = g_W2; Kpad = K2PAD; }
    else                 { A = g_Ax; W = g_W3; Kpad = K2PAD; }
    const int NT = Kpad / BK;

    // m-strip swizzle for L2 reuse: strips of 8 m-groups, n fastest
    const int bx = blockIdx.x;
    const int strip = bx / (8 * ngrp);
    const int rem   = bx % (8 * ngrp);
    const int mg    = strip * 8 + (rem % 8);
    const int ng    = rem / 8;
    const int m0 = mg * BM;
    const int n0 = ng * BN;

    extern __shared__ char smem_raw[];
    const uint32_t sbase = smem_u32(smem_raw);

    const int tid = threadIdx.x;
    const int wid = tid >> 5;
    const int lid = tid & 31;
    const int wm = (wid & 1) * 64;
    const int wn = (wid >> 1) * 32;

    auto load_chunk = [&](int t, int slot) {
        const uint32_t st = sbase + (uint32_t)slot * STAGE_BYTES;
        const int kc = t * BK;
#pragma unroll
        for (int i = 0; i < 4; i++) {
            const int u = tid + i * 256;
            const int r = u >> 3, c = u & 7;
            const uint32_t so = (uint32_t)(r * ROWB + c * 16);
            CP_ASYNC16(st + OFF_A + so, A + (size_t)(m0 + r) * Kpad + kc + c * 8);
            CP_ASYNC16(st + OFF_B + so, W + (size_t)(n0 + r) * Kpad + kc + c * 8);
        }
        CP_COMMIT();
    };

    float d[4][4][4];
#pragma unroll
    for (int mi = 0; mi < 4; mi++)
#pragma unroll
        for (int ni = 0; ni < 4; ni++)
#pragma unroll
            for (int q = 0; q < 4; q++) d[mi][ni][q] = 0.0f;

    const uint32_t a_row = (uint32_t)(wm + (lid & 15));
    const uint32_t a_kb  = (uint32_t)((lid >> 4) * 16);
    const uint32_t b_row = (uint32_t)(wn + (lid & 7) + ((lid >> 4) & 1) * 8);
    const uint32_t b_kb  = (uint32_t)(((lid >> 3) & 1) * 16);

    // Double-buffered register fragments
    uint32_t af[2][4][4];
    uint32_t bf[2][4][2];

    auto load_frags = [&](uint32_t st, int ks, int buf) {
        const uint32_t kbyte = (uint32_t)(ks * 32);
#pragma unroll
        for (int mi = 0; mi < 4; mi++) {
            const uint32_t ra = st + OFF_A + (a_row + mi * 16) * ROWB + kbyte + a_kb;
            LDSM_X4(af[buf][mi][0], af[buf][mi][1], af[buf][mi][2], af[buf][mi][3], ra);
        }
#pragma unroll
        for (int j = 0; j < 2; j++) {
            const uint32_t rb = st + OFF_B + (b_row + j * 16) * ROWB + kbyte + b_kb;
            LDSM_X4(bf[buf][2*j][0], bf[buf][2*j][1], bf[buf][2*j+1][0], bf[buf][2*j+1][1], rb);
        }
    };

    // Prologue: fill 2 of 3 stages
    load_chunk(0, 0);
    load_chunk(1, 1);

    for (int t = 0; t < NT; ++t) {
        CP_WAIT(1);            // chunk t landed (t+1 may still be in flight)
        __syncthreads();       // all warps done with slot being refilled

        if (t + 2 < NT) load_chunk(t + 2, (t + 2) % NSTAGE);
        else CP_COMMIT();      // keep outstanding-group count uniform

        const uint32_t st = sbase + (uint32_t)(t % NSTAGE) * STAGE_BYTES;

        load_frags(st, 0, 0);
#pragma unroll
        for (int ks = 0; ks < 4; ks++) {
            const int cur = ks & 1;
            if (ks < 3) load_frags(st, ks + 1, cur ^ 1);
#pragma unroll
            for (int mi = 0; mi < 4; mi++)
#pragma unroll
                for (int ni = 0; ni < 4; ni++)
                    MMA_FP16(d[mi][ni], af[cur][mi], bf[cur][ni][0], bf[cur][ni][1]);
        }
    }

    __syncthreads();

    // Epilogue: bias + activation + fp16 store
    const int er = lid >> 2;
    const int ec = (lid & 3) * 2;
#pragma unroll
    for (int mi = 0; mi < 4; mi++) {
#pragma unroll
        for (int ni = 0; ni < 4; ni++) {
            const int n = n0 + wn + ni * 8 + ec;     // even; H_DIM even -> no straddle
            if (n >= N3H) continue;
            const int m = m0 + wm + mi * 16 + er;
            const float2 bs = *(const float2*)(bias + n);
            const bool tA = (n < H_DIM);
            {
                const float y0 = d[mi][ni][0] + bs.x;
                const float y1 = d[mi][ni][1] + bs.y;
                const float v0 = tA ? tanh_fast(y0) : sigmoid_f(y0);
                const float v1 = tA ? tanh_fast(y1) : sigmoid_f(y1);
                *(__half2*)(g_gates + (size_t)m * N3H + n) = __floats2half2_rn(v0, v1);
            }
            {
                const float y0 = d[mi][ni][2] + bs.x;
                const float y1 = d[mi][ni][3] + bs.y;
                const float v0 = tA ? tanh_fast(y0) : sigmoid_f(y0);
                const float v1 = tA ? tanh_fast(y1) : sigmoid_f(y1);
                *(__half2*)(g_gates + (size_t)(m + 8) * N3H + n) = __floats2half2_rn(v0, v1);
            }
        }
    }
}

// ---------------------------------------------------------------------------
// fo-pool scan: 2 h-lanes/thread, raw-uint32 prefetch FIFOs.
// Modes 0/1 (Z,F,O): depth 16. Mode 2 (Z,F): depth 32.
// ---------------------------------------------------------------------------
__device__ __forceinline__ float2 cvt_h2(uint32_t u) {
    return __half22float2(*(const __half2*)&u);
}
__device__ __forceinline__ uint32_t ld_u32(const __half* p) {
    return *(const uint32_t*)p;
}

template <int MODE>
__global__ void scan_kernel(const int* __restrict__ sent_len,
                            float* __restrict__ out)
{
    const int tix = blockIdx.x * blockDim.x + threadIdx.x;
    if (tix >= (B_SZ * H_DIM) / 2) return;
    const int flat = tix * 2;
    const int b = flat / H_DIM;
    const int h = flat - b * H_DIM;       // even; H_DIM even -> no b straddle

    const size_t stride = (size_t)B_SZ * N3H;
    const __half* gp = g_gates + (size_t)b * N3H + h;

    float2 c = make_float2(0.f, 0.f);

    if (MODE != 2) {
        const int SD = 16;
        uint32_t zr[SD], fr[SD], orr[SD];
#pragma unroll
        for (int i = 0; i < SD; i++) {
            const __half* q = gp + (size_t)i * stride;
            zr[i]  = ld_u32(q);
            fr[i]  = ld_u32(q + H_DIM);
            orr[i] = ld_u32(q + 2 * H_DIM);
        }
        size_t xbase = (size_t)b * K2PAD + h;
        const size_t xstride = (size_t)B_SZ * K2PAD;
#pragma unroll 16
        for (int s = 0; s < S_LEN; ++s) {
            const int j = s & (SD - 1);
            const float2 z = cvt_h2(zr[j]);
            const float2 f = cvt_h2(fr[j]);
            const float2 o = cvt_h2(orr[j]);
            if (s + SD < S_LEN) {
                const __half* q = gp + (size_t)(s + SD) * stride;
                zr[j]  = ld_u32(q);
                fr[j]  = ld_u32(q + H_DIM);
                orr[j] = ld_u32(q + 2 * H_DIM);
            }
            c.x = fmaf(f.x, c.x - z.x, z.x);
            c.y = fmaf(f.y, c.y - z.y, z.y);
            const __half2 hh = __floats2half2_rn(o.x * c.x, o.y * c.y);
            *(uint32_t*)(g_Ax + xbase) = *(const uint32_t*)&hh;
            xbase += xstride;
        }
    } else {
        const int SD = 32;
        uint32_t zr[SD], fr[SD];
#pragma unroll
        for (int i = 0; i < SD; i++) {
            const __half* q = gp + (size_t)i * stride;
            zr[i] = ld_u32(q);
            fr[i] = ld_u32(q + H_DIM);
        }
#pragma unroll 32
        for (int s = 0; s < S_LEN; ++s) {
            const int j = s & (SD - 1);
            const float2 z = cvt_h2(zr[j]);
            const float2 f = cvt_h2(fr[j]);
            if (s + SD < S_LEN) {
                const __half* q = gp + (size_t)(s + SD) * stride;
                zr[j] = ld_u32(q);
                fr[j] = ld_u32(q + H_DIM);
            }
            c.x = fmaf(f.x, c.x - z.x, z.x);
            c.y = fmaf(f.y, c.y - z.y, z.y);
        }
    }

    if (MODE == 0) {
        *(float2*)(g_acc + flat) = c;
    } else if (MODE == 1) {
        float2 a = *(const float2*)(g_acc + flat);
        a.x += c.x; a.y += c.y;
        *(float2*)(g_acc + flat) = a;
    } else {
        const float inv = 1.0f / (float)sent_len[b];
        float2 a = *(const float2*)(g_acc + flat);
        float2 v;
        v.x = (a.x + c.x) * inv;
        v.y = (a.y + c.y) * inv;
        *(float2*)(out + flat) = v;
    }
}

// ---------------------------------------------------------------------------
extern "C" void kernel_launch(void* const* d_in, const int* in_sizes, int n_in,
                              void* d_out, int out_size)
{
    const float* sent     = (const float*)d_in[0];
    const int*   sent_len = (const int*)  d_in[1];
    const float* W1 = (const float*)d_in[2];
    const float* b1 = (const float*)d_in[3];
    const float* W2 = (const float*)d_in[4];
    const float* b2 = (const float*)d_in[5];
    const float* W3 = (const float*)d_in[6];
    const float* b3 = (const float*)d_in[7];
    float* out = (float*)d_out;

    cudaFuncSetAttribute(gemm_tc, cudaFuncAttributeMaxDynamicSharedMemorySize, GEMM_SMEM_BYTES);

    cvt_all<<<(G_TOTAL + 255) / 256, 256>>>(sent, W1, W2, W3);

    const int nblocks_full = (M_ROWS / BM) * NGRP_FULL;   // 64 * 57 = 3648
    const int nblocks_l3   = (M_ROWS / BM) * NGRP_L3;     // 64 * 38 = 2432
    const int sblocks = ((B_SZ * H_DIM) / 2 + 127) / 128; // 300

    gemm_tc<<<nblocks_full, 256, GEMM_SMEM_BYTES>>>(1, b1, NGRP_FULL);
    scan_kernel<0><<<sblocks, 128>>>(sent_len, out);

    gemm_tc<<<nblocks_full, 256, GEMM_SMEM_BYTES>>>(2, b2, NGRP_FULL);
    scan_kernel<1><<<sblocks, 128>>>(sent_len, out);

    // Layer 3: O-gate columns (n >= 4800) are never read (scan mode 2 uses
    // only Z and F, and layer-3 hidden output is unused) -> skip them.
    gemm_tc<<<nblocks_l3, 256, GEMM_SMEM_BYTES>>>(3, b3, NGRP_L3);
    scan_kernel<2><<<sblocks, 128>>>(sent_len, out);
}